// round 12
// baseline (speedup 1.0000x reference)
#include <cuda_runtime.h>
#include <cuda_bf16.h>
#include <math.h>
#include <stdint.h>

// ---------------- problem constants ----------------
#define L 512
#define NSEQ 256
#define DM 64
#define DS 32
#define NH 4
#define DK 32
#define DV 16
#define FFH 256
#define NROWS (NSEQ * L)
#define EPSLN 1e-5f
#define NEGMAX (-3.402823466e38f)

// ---------------- scratch ----------------
__device__ float g_q[L * NH * DK];
__device__ float g_k[L * NH * DK];
__device__ float g_attn[NH * L * L];          // A-frag: [h][iblk(4)][kc(16)][4096]
__device__ float g_vT[NH * L * NSEQ * DV];    // B-frag: [h][nblk(32)][kc(16)][4096]
__device__ float g_attout[NROWS * DM];        // A-frag 64-row tiles: [tile][4096]
__device__ float g_msax[NROWS * DM];          // raw rows

__device__ __forceinline__ void mma_tf32(float& c0, float& c1, float& c2, float& c3,
                                         uint32_t a0, uint32_t a1, uint32_t a2, uint32_t a3,
                                         uint32_t b0, uint32_t b1) {
    asm volatile(
        "mma.sync.aligned.m16n8k8.row.col.f32.tf32.tf32.f32 "
        "{%0,%1,%2,%3}, {%4,%5,%6,%7}, {%8,%9}, {%0,%1,%2,%3};"
        : "+f"(c0), "+f"(c1), "+f"(c2), "+f"(c3)
        : "r"(a0), "r"(a1), "r"(a2), "r"(a3), "r"(b0), "r"(b1));
}
#define F2U(x) __float_as_uint(x)

__device__ __forceinline__ uint32_t smem_u32(const void* p) {
    uint32_t a;
    asm("{ .reg .u64 tmp; cvta.to.shared.u64 tmp, %1; cvt.u32.u64 %0, tmp; }"
        : "=r"(a) : "l"(p));
    return a;
}
__device__ __forceinline__ void cp16(uint32_t smem, const void* gmem) {
    asm volatile("cp.async.cg.shared.global [%0], [%1], 16;" :: "r"(smem), "l"(gmem));
}
#define CP_COMMIT() asm volatile("cp.async.commit_group;")
#define CP_WAIT2()  asm volatile("cp.async.wait_group 2;")

__device__ __forceinline__ int afrag_addr(int r, int c, int KS8) {
    return ((r >> 4) * KS8 + (c >> 3)) * 128 + (r & 7) * 16 + ((r >> 3) & 1)
         + (c & 3) * 4 + ((c >> 2) & 1) * 2;
}
__device__ __forceinline__ int bfrag_addr(int c, int n, int KS8) {
    return ((n >> 3) * KS8 + (c >> 3)) * 64 + (n & 7) * 8 + (c & 3) * 2 + ((c >> 2) & 1);
}

// =====================================================================
// K1: st = LN(state); q,k projections.  grid=512, block=128
// =====================================================================
__global__ void qk_kernel(const float* __restrict__ state,
                          const float* __restrict__ nsg, const float* __restrict__ nsb,
                          const float* __restrict__ Wq, const float* __restrict__ bq,
                          const float* __restrict__ Wk, const float* __restrict__ bk) {
    int l = blockIdx.x;
    int t = threadIdx.x;
    __shared__ float st[DS];
    if (t < DS) {
        float x = state[l * DS + t];
        float s = x;
        #pragma unroll
        for (int o = 16; o; o >>= 1) s += __shfl_xor_sync(0xffffffffu, s, o);
        float m = s * (1.0f / DS);
        float d = x - m;
        float v = d * d;
        #pragma unroll
        for (int o = 16; o; o >>= 1) v += __shfl_xor_sync(0xffffffffu, v, o);
        float r = rsqrtf(v * (1.0f / DS) + EPSLN);
        st[t] = d * r * nsg[t] + nsb[t];
    }
    __syncthreads();
    float aq = bq[t], ak = bk[t];
    #pragma unroll
    for (int c = 0; c < DS; c++) {
        float s = st[c];
        aq += s * Wq[c * 128 + t];
        ak += s * Wk[c * 128 + t];
    }
    g_q[l * 128 + t] = aq;
    g_k[l * 128 + t] = ak;
}

// =====================================================================
// K2 (fused): blocks [0,2048) = v path (1 tile each);
//             blocks [2048,4096) = attn softmax.
// =====================================================================
__global__ void __launch_bounds__(256) prep_kernel(
        const float* __restrict__ Ca,
        const float* __restrict__ msa,
        const float* __restrict__ n1g, const float* __restrict__ n1b,
        const float* __restrict__ Wv, const float* __restrict__ bv) {
    __shared__ float Wvp[4096];
    __shared__ float Ap[4096];
    __shared__ float sbv[DM], sg[DM], sb[DM];
    __shared__ float qv[DK];
    __shared__ float red[8];
    __shared__ float cai[3];

    int t = threadIdx.x;

    if (blockIdx.x < 2048) {
        int warp = t >> 5, lane = t & 31;
        int rg = lane >> 2, q2 = (lane & 3) * 2;
        for (int i = t; i < 4096; i += 256) {
            int c = i >> 6, n = i & 63;
            Wvp[bfrag_addr(c, n, 8)] = Wv[i];
        }
        if (t < DM) { sbv[t] = bv[t]; sg[t] = n1g[t]; sb[t] = n1b[t]; }
        __syncthreads();

        int wm = warp >> 2, wn = warp & 3;
        int tile = blockIdx.x;
        size_t row0 = (size_t)tile * 64;
        #pragma unroll
        for (int rr = 0; rr < 8; rr++) {
            int row = warp * 8 + rr;
            float2 x2 = *(const float2*)&msa[(row0 + row) * DM + 2 * lane];
            float sum = x2.x + x2.y;
            #pragma unroll
            for (int o = 16; o; o >>= 1) sum += __shfl_xor_sync(0xffffffffu, sum, o);
            float m = sum * (1.0f / DM);
            float d0 = x2.x - m, d1 = x2.y - m;
            float vv = d0 * d0 + d1 * d1;
            #pragma unroll
            for (int o = 16; o; o >>= 1) vv += __shfl_xor_sync(0xffffffffu, vv, o);
            float r = rsqrtf(vv * (1.0f / DM) + EPSLN);
            int c0 = 2 * lane;
            Ap[afrag_addr(row, c0, 8)]     = d0 * r * sg[c0]     + sb[c0];
            Ap[afrag_addr(row, c0 + 1, 8)] = d1 * r * sg[c0 + 1] + sb[c0 + 1];
        }
        __syncthreads();
        float acc[2][2][4];
        #pragma unroll
        for (int x = 0; x < 2; x++)
            #pragma unroll
            for (int y = 0; y < 2; y++)
                #pragma unroll
                for (int r = 0; r < 4; r++) acc[x][y][r] = 0.0f;
        #pragma unroll
        for (int ks = 0; ks < 8; ks++) {
            float4 af[2];
            float2 bf[2];
            #pragma unroll
            for (int mt = 0; mt < 2; mt++)
                af[mt] = *(const float4*)&Ap[((wm * 2 + mt) * 8 + ks) * 128 + lane * 4];
            #pragma unroll
            for (int nt = 0; nt < 2; nt++)
                bf[nt] = *(const float2*)&Wvp[((wn * 2 + nt) * 8 + ks) * 64 + lane * 2];
            #pragma unroll
            for (int mt = 0; mt < 2; mt++)
                #pragma unroll
                for (int nt = 0; nt < 2; nt++)
                    mma_tf32(acc[mt][nt][0], acc[mt][nt][1], acc[mt][nt][2], acc[mt][nt][3],
                             F2U(af[mt].x), F2U(af[mt].y), F2U(af[mt].z), F2U(af[mt].w),
                             F2U(bf[nt].x), F2U(bf[nt].y));
        }
        __syncthreads();
        #pragma unroll
        for (int mt = 0; mt < 2; mt++) {
            #pragma unroll
            for (int nt = 0; nt < 2; nt++) {
                int rt0 = wm * 32 + mt * 16 + rg;
                int c0 = wn * 16 + nt * 8 + q2;
                #pragma unroll
                for (int e = 0; e < 4; e++) {
                    int rt = rt0 + (e >> 1) * 8;
                    int cc = c0 + (e & 1);
                    int h = cc >> 4, d = cc & 15;
                    int sidx = ((((h * 2 + (rt >> 5)) * 2 + (d >> 3)) * 4)
                                + ((rt >> 3) & 3)) * 64
                             + (d & 7) * 8 + (rt & 3) * 2 + ((rt >> 2) & 1);
                    Ap[sidx] = acc[mt][nt][e] + sbv[cc];
                }
            }
        }
        __syncthreads();
        {
            int n = (int)(row0 >> 9);
            int j0s = (int)((row0 & 511) >> 5);
            int blk = n >> 3;
            #pragma unroll
            for (int u = 0; u < 4; u++) {
                int f = t + u * 256;
                int b = f >> 4;
                int off = (f & 15) * 4;
                int h = b >> 4, kcl = (b >> 3) & 1, dhi = (b >> 2) & 1, krhi = b & 3;
                size_t dst = ((size_t)(h * 32 + blk) * 16 + j0s + kcl) * 4096
                           + (size_t)((((n & 7) * 2 + dhi) * 4 + krhi) * 64 + off);
                *(float4*)&g_vT[dst] = *(const float4*)&Ap[b * 64 + off];
            }
        }
    } else {
        int idx = blockIdx.x - 2048;
        int i = idx & 511, h = idx >> 9;
        if (t < DK) qv[t] = g_q[i * 128 + h * DK + t];
        if (t < 3)  cai[t] = Ca[i * 3 + t];
        __syncthreads();

        float bin = (float)(4 * (h + 1)) / 10.0f;
        float bin2 = bin * bin;
        const float scaling = 0.17677669529663687f;
        float cx = cai[0], cy = cai[1], cz = cai[2];

        float sc[2];
        #pragma unroll
        for (int u = 0; u < 2; u++) {
            int j = t + u * 256;
            float dx = Ca[3 * j] - cx, dy = Ca[3 * j + 1] - cy, dz = Ca[3 * j + 2] - cz;
            float sq = fmaxf(dx * dx + dy * dy + dz * dz, 1e-12f);
            if (sq > bin2) {
                sc[u] = NEGMAX;
            } else {
                float a = 0.0f;
                const float* kp = &g_k[j * 128 + h * DK];
                #pragma unroll
                for (int d = 0; d < DK; d++) a += qv[d] * kp[d];
                sc[u] = a * scaling;
            }
        }
        float mx = fmaxf(sc[0], sc[1]);
        #pragma unroll
        for (int o = 16; o; o >>= 1) mx = fmaxf(mx, __shfl_xor_sync(0xffffffffu, mx, o));
        if ((t & 31) == 0) red[t >> 5] = mx;
        __syncthreads();
        mx = red[0];
        #pragma unroll
        for (int w = 1; w < 8; w++) mx = fmaxf(mx, red[w]);

        float e0 = expf(sc[0] - mx);
        float e1 = expf(sc[1] - mx);
        float ss = e0 + e1;
        #pragma unroll
        for (int o = 16; o; o >>= 1) ss += __shfl_xor_sync(0xffffffffu, ss, o);
        __syncthreads();
        if ((t & 31) == 0) red[t >> 5] = ss;
        __syncthreads();
        ss = red[0];
        #pragma unroll
        for (int w = 1; w < 8; w++) ss += red[w];
        float inv = 1.0f / ss;

        int iblk = i >> 7, ib = i & 127;
        size_t blkbase = ((size_t)(h * 4 + iblk) * 16) * 4096;
        float vals[2] = {e0 * inv, e1 * inv};
        #pragma unroll
        for (int u = 0; u < 2; u++) {
            int j = t + u * 256;
            int kc = j >> 5;
            g_attn[blkbase + (size_t)kc * 4096 + afrag_addr(ib, j & 31, 4)] = vals[u];
        }
    }
}

// =====================================================================
// K3 (mma tf32 + cp.async 3-stage): per-head C = attn @ vT.  grid=(32,4,4)
// =====================================================================
extern __shared__ float gsh[];
__global__ void __launch_bounds__(256, 2) gemm_attn_mma() {
    int h  = blockIdx.z;
    const float* __restrict__ Abase =
        g_attn + ((size_t)(h * 4 + blockIdx.y) * 16) * 4096;
    const float* __restrict__ Bbase =
        g_vT + ((size_t)(h * 32 + blockIdx.x) * 16) * 4096;

    float* sA = gsh;
    float* sB = gsh + 12288;

    int t = threadIdx.x, wid = t >> 5, lid = t & 31;
    int wm = wid >> 2, wn = wid & 3;
    uint32_t aAddr = smem_u32(sA) + t * 16;
    uint32_t bAddr = smem_u32(sB) + t * 16;

    float acc[4][4][4];
    #pragma unroll
    for (int x = 0; x < 4; x++)
        #pragma unroll
        for (int y = 0; y < 4; y++)
            #pragma unroll
            for (int r = 0; r < 4; r++) acc[x][y][r] = 0.0f;

    #pragma unroll 1
    for (int p = 0; p < 2; p++) {
        const float4* srcA = (const float4*)(Abase + (size_t)p * 4096) + t;
        const float4* srcB = (const float4*)(Bbase + (size_t)p * 4096) + t;
        #pragma unroll
        for (int u = 0; u < 4; u++) {
            cp16(aAddr + p * 16384 + u * 4096, srcA + u * 256);
            cp16(bAddr + p * 16384 + u * 4096, srcB + u * 256);
        }
        CP_COMMIT();
    }

    #pragma unroll 1
    for (int kc = 0; kc < 16; kc++) {
        if (kc + 2 < 16) {
            int st = (kc + 2) % 3;
            const float4* srcA = (const float4*)(Abase + (size_t)(kc + 2) * 4096) + t;
            const float4* srcB = (const float4*)(Bbase + (size_t)(kc + 2) * 4096) + t;
            #pragma unroll
            for (int u = 0; u < 4; u++) {
                cp16(aAddr + st * 16384 + u * 4096, srcA + u * 256);
                cp16(bAddr + st * 16384 + u * 4096, srcB + u * 256);
            }
        }
        CP_COMMIT();
        CP_WAIT2();
        __syncthreads();
        const float* cA = sA + (kc % 3) * 4096;
        const float* cB = sB + (kc % 3) * 4096;
        #pragma unroll
        for (int ks = 0; ks < 4; ks++) {
            uint32_t bf[4][2];
            #pragma unroll
            for (int nt2 = 0; nt2 < 4; nt2++) {
                int nt = wn * 4 + nt2;
                float2 b2 = *(const float2*)&cB[(nt * 4 + ks) * 64 + lid * 2];
                bf[nt2][0] = F2U(b2.x);
                bf[nt2][1] = F2U(b2.y);
            }
            #pragma unroll
            for (int mt2 = 0; mt2 < 4; mt2++) {
                int mt = wm * 4 + mt2;
                float4 a4 = *(const float4*)&cA[(mt * 4 + ks) * 128 + lid * 4];
                #pragma unroll
                for (int nt2 = 0; nt2 < 4; nt2++)
                    mma_tf32(acc[mt2][nt2][0], acc[mt2][nt2][1],
                             acc[mt2][nt2][2], acc[mt2][nt2][3],
                             F2U(a4.x), F2U(a4.y), F2U(a4.z), F2U(a4.w),
                             bf[nt2][0], bf[nt2][1]);
            }
        }
        __syncthreads();
    }

    float* stg = gsh;
    int rg = lid >> 2, q2 = (lid & 3) * 2;
    #pragma unroll
    for (int mt2 = 0; mt2 < 4; mt2++) {
        #pragma unroll
        for (int nt2 = 0; nt2 < 4; nt2++) {
            int nloc = wn * 2 + (nt2 >> 1);
            #pragma unroll
            for (int e = 0; e < 4; e++) {
                int rt = mt2 * 16 + rg + (e >> 1) * 8;
                int d = (nt2 & 1) * 8 + q2 + (e & 1);
                int sidx = (((wm * 8 + nloc) * 2 + (d >> 3)) * 4 + mt2) * 128
                         + (rt & 7) * 16 + ((rt >> 3) & 1)
                         + (d & 3) * 4 + ((d >> 2) & 1) * 2;
                stg[sidx] = acc[mt2][nt2][e];
            }
        }
    }
    __syncthreads();
    #pragma unroll
    for (int u = 0; u < 16; u++) {
        int f = t + u * 256;
        int b = f >> 5;
        int off = (f & 31) * 4;
        int krt = b & 3, dhi = (b >> 2) & 1, nloc = (b >> 3) & 7, iloc = b >> 6;
        int n = blockIdx.x * 8 + nloc;
        size_t rtile = (size_t)n * 8 + blockIdx.y * 2 + iloc;
        size_t dst = rtile * 4096 + (size_t)((krt * 8 + h * 2 + dhi) * 128 + off);
        *(float4*)&g_attout[dst] = *(const float4*)&stg[b * 128 + off];
    }
}

// =====================================================================
// K5 (mma tf32): msax = msa + attout@Wo + bo.  grid=2048, 1 tile/CTA,
// residual msa prefetched into registers before the mma phase.
// =====================================================================
__global__ void __launch_bounds__(256) oproj_mma_kernel(
        const float* __restrict__ msa,
        const float* __restrict__ Wo, const float* __restrict__ bo) {
    __shared__ float Wop[4096];
    __shared__ float Ap[4096];
    __shared__ float sbo[DM];
    int t = threadIdx.x, warp = t >> 5, lane = t & 31;
    int rg = lane >> 2, q2 = (lane & 3) * 2;
    int wm = warp >> 2, wn = warp & 3;

    int tile = blockIdx.x;
    size_t row0 = (size_t)tile * 64;

    // start Ap load (vector copy) + weight permute + residual prefetch
    for (int i = t; i < 4096; i += 256) {
        int c = i >> 6, n = i & 63;
        Wop[bfrag_addr(c, n, 8)] = Wo[i];
    }
    const float4* src = (const float4*)(g_attout + (size_t)tile * 4096);
    #pragma unroll
    for (int u = 0; u < 4; u++) {
        int id = t + u * 256;
        *(float4*)&Ap[id * 4] = src[id];
    }
    // prefetch residual into regs (epilogue-mapped)
    float2 mres[2][2][2];
    #pragma unroll
    for (int mt = 0; mt < 2; mt++)
        #pragma unroll
        for (int nt = 0; nt < 2; nt++) {
            int rt0 = wm * 32 + mt * 16 + rg;
            int c0 = wn * 16 + nt * 8 + q2;
            #pragma unroll
            for (int half = 0; half < 2; half++)
                mres[mt][nt][half] =
                    *(const float2*)&msa[(row0 + rt0 + half * 8) * DM + c0];
        }
    if (t < DM) sbo[t] = bo[t];
    __syncthreads();

    float acc[2][2][4];
    #pragma unroll
    for (int x = 0; x < 2; x++)
        #pragma unroll
        for (int y = 0; y < 2; y++)
            #pragma unroll
            for (int r = 0; r < 4; r++) acc[x][y][r] = 0.0f;
    #pragma unroll
    for (int ks = 0; ks < 8; ks++) {
        float4 af[2];
        float2 bf[2];
        #pragma unroll
        for (int mt = 0; mt < 2; mt++)
            af[mt] = *(const float4*)&Ap[((wm * 2 + mt) * 8 + ks) * 128 + lane * 4];
        #pragma unroll
        for (int nt = 0; nt < 2; nt++)
            bf[nt] = *(const float2*)&Wop[((wn * 2 + nt) * 8 + ks) * 64 + lane * 2];
        #pragma unroll
        for (int mt = 0; mt < 2; mt++)
            #pragma unroll
            for (int nt = 0; nt < 2; nt++)
                mma_tf32(acc[mt][nt][0], acc[mt][nt][1], acc[mt][nt][2], acc[mt][nt][3],
                         F2U(af[mt].x), F2U(af[mt].y), F2U(af[mt].z), F2U(af[mt].w),
                         F2U(bf[nt].x), F2U(bf[nt].y));
    }
    #pragma unroll
    for (int mt = 0; mt < 2; mt++) {
        #pragma unroll
        for (int nt = 0; nt < 2; nt++) {
            int rt0 = wm * 32 + mt * 16 + rg;
            int c0 = wn * 16 + nt * 8 + q2;
            float bo0 = sbo[c0], bo1 = sbo[c0 + 1];
            #pragma unroll
            for (int half = 0; half < 2; half++) {
                size_t r = row0 + rt0 + half * 8;
                float2 m2 = mres[mt][nt][half];
                *(float2*)&g_msax[r * DM + c0] =
                    make_float2(acc[mt][nt][half * 2]     + bo0 + m2.x,
                                acc[mt][nt][half * 2 + 1] + bo1 + m2.y);
            }
        }
    }
}

// =====================================================================
// K6 (mma tf32, 512 threads): fused FF + final LN.
// 16 warps: GEMM1 2m x 8n; GEMM2 2m x 2n x 4k-split (partials in Ps).
// =====================================================================
struct FFS4 {
    float W1p[DM * FFH];
    float W2p[FFH * DM];
    float b1s[FFH];
    float b2s[DM], g2[DM], bn2[DM], g3[DM], bn3[DM];
    float Xs[64 * DM];
    float Ap[64 * DM];
    float Hp[64 * FFH];
};
extern __shared__ unsigned char ff_raw[];

__global__ void __launch_bounds__(512) ff_mma_kernel(
        const float* __restrict__ n2g, const float* __restrict__ n2b,
        const float* __restrict__ W1, const float* __restrict__ b1,
        const float* __restrict__ W2, const float* __restrict__ b2,
        const float* __restrict__ n3g, const float* __restrict__ n3b,
        float* __restrict__ out) {
    FFS4* s = (FFS4*)ff_raw;
    int t = threadIdx.x, warp = t >> 5, lane = t & 31;
    int rg = lane >> 2, q2 = (lane & 3) * 2;

    for (int i = t; i < DM * FFH; i += 512) {
        int c = i >> 8, n = i & 255;
        s->W1p[bfrag_addr(c, n, 8)] = W1[i];
    }
    for (int i = t; i < FFH * DM; i += 512) {
        int c = i >> 6, n = i & 63;
        s->W2p[bfrag_addr(c, n, 32)] = W2[i];
    }
    if (t < FFH) s->b1s[t] = b1[t];
    if (t < DM) { s->b2s[t] = b2[t]; s->g2[t] = n2g[t]; s->bn2[t] = n2b[t];
                  s->g3[t] = n3g[t]; s->bn3[t] = n3b[t]; }
    __syncthreads();

    const int nTiles = NROWS / 64;
    float4 xr[2];
    if (blockIdx.x < nTiles) {
        const float4* src = (const float4*)&g_msax[(size_t)blockIdx.x * 4096];
        #pragma unroll
        for (int i = 0; i < 2; i++) xr[i] = src[t * 2 + i];
    }

    for (int tile = blockIdx.x; tile < nTiles; tile += gridDim.x) {
        size_t row0 = (size_t)tile * 64;
        #pragma unroll
        for (int i = 0; i < 2; i++)
            *(float4*)&s->Xs[(t * 2 + i) * 4] = xr[i];
        __syncthreads();
        int nxt = tile + gridDim.x;
        if (nxt < nTiles) {
            const float4* src = (const float4*)&g_msax[(size_t)nxt * 4096];
            #pragma unroll
            for (int i = 0; i < 2; i++) xr[i] = src[t * 2 + i];
        }
        #pragma unroll
        for (int rr = 0; rr < 4; rr++) {
            int row = warp * 4 + rr;
            float2 x2 = *(const float2*)&s->Xs[row * DM + 2 * lane];
            float sum = x2.x + x2.y;
            #pragma unroll
            for (int o = 16; o; o >>= 1) sum += __shfl_xor_sync(0xffffffffu, sum, o);
            float m = sum * (1.0f / DM);
            float d0 = x2.x - m, d1 = x2.y - m;
            float vv = d0 * d0 + d1 * d1;
            #pragma unroll
            for (int o = 16; o; o >>= 1) vv += __shfl_xor_sync(0xffffffffu, vv, o);
            float r = rsqrtf(vv * (1.0f / DM) + EPSLN);
            int c0 = 2 * lane;
            s->Ap[afrag_addr(row, c0, 8)]     = d0 * r * s->g2[c0]     + s->bn2[c0];
            s->Ap[afrag_addr(row, c0 + 1, 8)] = d1 * r * s->g2[c0 + 1] + s->bn2[c0 + 1];
        }
        __syncthreads();
        {
            int wm = warp >> 3, wn = warp & 7;
            float acc1[2][4][4];
            #pragma unroll
            for (int x = 0; x < 2; x++)
                #pragma unroll
                for (int y = 0; y < 4; y++)
                    #pragma unroll
                    for (int r = 0; r < 4; r++) acc1[x][y][r] = 0.0f;
            #pragma unroll
            for (int ks = 0; ks < 8; ks++) {
                float4 af0 = *(const float4*)&s->Ap[((wm * 2 + 0) * 8 + ks) * 128 + lane * 4];
                float4 af1 = *(const float4*)&s->Ap[((wm * 2 + 1) * 8 + ks) * 128 + lane * 4];
                #pragma unroll
                for (int nt = 0; nt < 4; nt++) {
                    float2 b2v = *(const float2*)&s->W1p[((wn * 4 + nt) * 8 + ks) * 64 + lane * 2];
                    mma_tf32(acc1[0][nt][0], acc1[0][nt][1], acc1[0][nt][2], acc1[0][nt][3],
                             F2U(af0.x), F2U(af0.y), F2U(af0.z), F2U(af0.w),
                             F2U(b2v.x), F2U(b2v.y));
                    mma_tf32(acc1[1][nt][0], acc1[1][nt][1], acc1[1][nt][2], acc1[1][nt][3],
                             F2U(af1.x), F2U(af1.y), F2U(af1.z), F2U(af1.w),
                             F2U(b2v.x), F2U(b2v.y));
                }
            }
            #pragma unroll
            for (int mt = 0; mt < 2; mt++) {
                int mtg = wm * 2 + mt;
                #pragma unroll
                for (int nt = 0; nt < 4; nt++) {
                    int ks2 = wn * 4 + nt;
                    int c0 = ks2 * 8 + q2;
                    float b1a = s->b1s[c0], b1b = s->b1s[c0 + 1];
                    float v0 = fmaxf(acc1[mt][nt][0] + b1a, 0.f);
                    float v1 = fmaxf(acc1[mt][nt][1] + b1b, 0.f);
                    float v2 = fmaxf(acc1[mt][nt][2] + b1a, 0.f);
                    float v3 = fmaxf(acc1[mt][nt][3] + b1b, 0.f);
                    int fb = (mtg * 32 + ks2) * 128 + rg * 16;
                    int a0 = fb + (q2 & 3) * 4 + ((q2 >> 2) << 1);
                    int kk1 = q2 + 1;
                    int a1 = fb + (kk1 & 3) * 4 + ((kk1 >> 2) << 1);
                    *(float2*)&s->Hp[a0] = make_float2(v0, v2);
                    *(float2*)&s->Hp[a1] = make_float2(v1, v3);
                }
            }
        }
        __syncthreads();
        {
            int kg = warp >> 2;
            int wm2 = (warp >> 1) & 1, wn2 = warp & 1;
            float acc2[2][4][4];
            #pragma unroll
            for (int x = 0; x < 2; x++)
                #pragma unroll
                for (int y = 0; y < 4; y++)
                    #pragma unroll
                    for (int r = 0; r < 4; r++) acc2[x][y][r] = 0.0f;
            #pragma unroll
            for (int ks = 0; ks < 8; ks++) {
                int ksg = kg * 8 + ks;
                float4 af0 = *(const float4*)&s->Hp[((wm2 * 2 + 0) * 32 + ksg) * 128 + lane * 4];
                float4 af1 = *(const float4*)&s->Hp[((wm2 * 2 + 1) * 32 + ksg) * 128 + lane * 4];
                #pragma unroll
                for (int nt = 0; nt < 4; nt++) {
                    float2 b2v = *(const float2*)&s->W2p[((wn2 * 4 + nt) * 32 + ksg) * 64 + lane * 2];
                    mma_tf32(acc2[0][nt][0], acc2[0][nt][1], acc2[0][nt][2], acc2[0][nt][3],
                             F2U(af0.x), F2U(af0.y), F2U(af0.z), F2U(af0.w),
                             F2U(b2v.x), F2U(b2v.y));
                    mma_tf32(acc2[1][nt][0], acc2[1][nt][1], acc2[1][nt][2], acc2[1][nt][3],
                             F2U(af1.x), F2U(af1.y), F2U(af1.z), F2U(af1.w),
                             F2U(b2v.x), F2U(b2v.y));
                }
            }
            __syncthreads();
            float* Ps = s->Ap;
            #pragma unroll
            for (int mt = 0; mt < 2; mt++)
                #pragma unroll
                for (int nt = 0; nt < 4; nt++) {
                    int r0 = wm2 * 32 + mt * 16 + rg;
                    int c0 = wn2 * 32 + nt * 8 + q2;
                    *(float2*)&Ps[kg * 4608 + r0 * 72 + c0] =
                        make_float2(acc2[mt][nt][0], acc2[mt][nt][1]);
                    *(float2*)&Ps[kg * 4608 + (r0 + 8) * 72 + c0] =
                        make_float2(acc2[mt][nt][2], acc2[mt][nt][3]);
                }
        }
        __syncthreads();
        {
            float* Ps = s->Ap;
            int row = t >> 3, c0 = (t & 7) * 8;
            #pragma unroll
            for (int i = 0; i < 2; i++) {
                int c = c0 + i * 4;
                float4 xv = *(const float4*)&s->Xs[row * DM + c];
                float4 bv = *(const float4*)&s->b2s[c];
                float4 p0 = *(const float4*)&Ps[row * 72 + c];
                float4 p1 = *(const float4*)&Ps[4608 + row * 72 + c];
                float4 p2 = *(const float4*)&Ps[9216 + row * 72 + c];
                float4 p3 = *(const float4*)&Ps[13824 + row * 72 + c];
                *(float4*)&s->Xs[row * DM + c] =
                    make_float4(xv.x + bv.x + p0.x + p1.x + p2.x + p3.x,
                                xv.y + bv.y + p0.y + p1.y + p2.y + p3.y,
                                xv.z + bv.z + p0.z + p1.z + p2.z + p3.z,
                                xv.w + bv.w + p0.w + p1.w + p2.w + p3.w);
            }
        }
        __syncthreads();
        #pragma unroll
        for (int rr = 0; rr < 4; rr++) {
            int row = warp * 4 + rr;
            float2 y2 = *(const float2*)&s->Xs[row * DM + 2 * lane];
            float sum = y2.x + y2.y;
            #pragma unroll
            for (int o = 16; o; o >>= 1) sum += __shfl_xor_sync(0xffffffffu, sum, o);
            float m = sum * (1.0f / DM);
            float d0 = y2.x - m, d1 = y2.y - m;
            float vv = d0 * d0 + d1 * d1;
            #pragma unroll
            for (int o = 16; o; o >>= 1) vv += __shfl_xor_sync(0xffffffffu, vv, o);
            float r = rsqrtf(vv * (1.0f / DM) + EPSLN);
            size_t ob = (row0 + row) * DM;
            out[ob + 2 * lane]     = d0 * r * s->g3[2 * lane]     + s->bn3[2 * lane];
            out[ob + 2 * lane + 1] = d1 * r * s->g3[2 * lane + 1] + s->bn3[2 * lane + 1];
        }
        __syncthreads();
    }
}

// =====================================================================
extern "C" void kernel_launch(void* const* d_in, const int* in_sizes, int n_in,
                              void* d_out, int out_size) {
    const float* msa   = (const float*)d_in[0];
    const float* Ca    = (const float*)d_in[1];
    const float* state = (const float*)d_in[2];
    const float* ns_g  = (const float*)d_in[3];
    const float* ns_b  = (const float*)d_in[4];
    const float* n1_g  = (const float*)d_in[5];
    const float* n1_b  = (const float*)d_in[6];
    const float* Wq    = (const float*)d_in[7];
    const float* bq    = (const float*)d_in[8];
    const float* Wk    = (const float*)d_in[9];
    const float* bk    = (const float*)d_in[10];
    const float* Wv    = (const float*)d_in[11];
    const float* bv    = (const float*)d_in[12];
    const float* Wo    = (const float*)d_in[13];
    const float* bo    = (const float*)d_in[14];
    const float* n2_g  = (const float*)d_in[15];
    const float* n2_b  = (const float*)d_in[16];
    const float* W1    = (const float*)d_in[17];
    const float* b1    = (const float*)d_in[18];
    const float* W2    = (const float*)d_in[19];
    const float* b2    = (const float*)d_in[20];
    const float* n3_g  = (const float*)d_in[21];
    const float* n3_b  = (const float*)d_in[22];
    float* out = (float*)d_out;

    cudaFuncSetAttribute(ff_mma_kernel, cudaFuncAttributeMaxDynamicSharedMemorySize,
                         (int)sizeof(FFS4));
    cudaFuncSetAttribute(gemm_attn_mma, cudaFuncAttributeMaxDynamicSharedMemorySize,
                         98304);

    qk_kernel<<<L, 128>>>(state, ns_g, ns_b, Wq, bq, Wk, bk);
    prep_kernel<<<4096, 256>>>(Ca, msa, n1_g, n1_b, Wv, bv);
    gemm_attn_mma<<<dim3(32, 4, 4), 256, 98304>>>();
    oproj_mma_kernel<<<2048, 256>>>(msa, Wo, bo);
    ff_mma_kernel<<<148, 512, sizeof(FFS4)>>>(n2_g, n2_b, W1, b1, W2, b2, n3_g, n3_b, out);
}

// round 14
// speedup vs baseline: 1.0466x; 1.0466x over previous
#include <cuda_runtime.h>
#include <cuda_bf16.h>
#include <math.h>
#include <stdint.h>

// ---------------- problem constants ----------------
#define L 512
#define NSEQ 256
#define DM 64
#define DS 32
#define NH 4
#define DK 32
#define DV 16
#define FFH 256
#define NROWS (NSEQ * L)
#define EPSLN 1e-5f
#define NEGMAX (-3.402823466e38f)

// ---------------- scratch ----------------
__device__ float g_q[L * NH * DK];
__device__ float g_k[L * NH * DK];
__device__ float g_attn[NH * L * L];          // A-frag: [h][iblk(4)][kc(16)][4096]
__device__ float g_vT[NH * L * NSEQ * DV];    // B-frag: [h][nblk(32)][kc(16)][4096]
__device__ float g_attout[NROWS * DM];        // A-frag 64-row tiles: [tile][4096]
__device__ float g_msax[NROWS * DM];          // raw rows

__device__ __forceinline__ void mma_tf32(float& c0, float& c1, float& c2, float& c3,
                                         uint32_t a0, uint32_t a1, uint32_t a2, uint32_t a3,
                                         uint32_t b0, uint32_t b1) {
    asm volatile(
        "mma.sync.aligned.m16n8k8.row.col.f32.tf32.tf32.f32 "
        "{%0,%1,%2,%3}, {%4,%5,%6,%7}, {%8,%9}, {%0,%1,%2,%3};"
        : "+f"(c0), "+f"(c1), "+f"(c2), "+f"(c3)
        : "r"(a0), "r"(a1), "r"(a2), "r"(a3), "r"(b0), "r"(b1));
}
#define F2U(x) __float_as_uint(x)

__device__ __forceinline__ uint32_t smem_u32(const void* p) {
    uint32_t a;
    asm("{ .reg .u64 tmp; cvta.to.shared.u64 tmp, %1; cvt.u32.u64 %0, tmp; }"
        : "=r"(a) : "l"(p));
    return a;
}
__device__ __forceinline__ void cp16(uint32_t smem, const void* gmem) {
    asm volatile("cp.async.cg.shared.global [%0], [%1], 16;" :: "r"(smem), "l"(gmem));
}
#define CP_COMMIT() asm volatile("cp.async.commit_group;")
#define CP_WAIT2()  asm volatile("cp.async.wait_group 2;")
#define CP_WAIT1()  asm volatile("cp.async.wait_group 1;")

__device__ __forceinline__ int afrag_addr(int r, int c, int KS8) {
    return ((r >> 4) * KS8 + (c >> 3)) * 128 + (r & 7) * 16 + ((r >> 3) & 1)
         + (c & 3) * 4 + ((c >> 2) & 1) * 2;
}
__device__ __forceinline__ int bfrag_addr(int c, int n, int KS8) {
    return ((n >> 3) * KS8 + (c >> 3)) * 64 + (n & 7) * 8 + (c & 3) * 2 + ((c >> 2) & 1);
}

// =====================================================================
// K1: st = LN(state); q,k projections.  grid=512, block=128
// =====================================================================
__global__ void qk_kernel(const float* __restrict__ state,
                          const float* __restrict__ nsg, const float* __restrict__ nsb,
                          const float* __restrict__ Wq, const float* __restrict__ bq,
                          const float* __restrict__ Wk, const float* __restrict__ bk) {
    int l = blockIdx.x;
    int t = threadIdx.x;
    __shared__ float st[DS];
    if (t < DS) {
        float x = state[l * DS + t];
        float s = x;
        #pragma unroll
        for (int o = 16; o; o >>= 1) s += __shfl_xor_sync(0xffffffffu, s, o);
        float m = s * (1.0f / DS);
        float d = x - m;
        float v = d * d;
        #pragma unroll
        for (int o = 16; o; o >>= 1) v += __shfl_xor_sync(0xffffffffu, v, o);
        float r = rsqrtf(v * (1.0f / DS) + EPSLN);
        st[t] = d * r * nsg[t] + nsb[t];
    }
    __syncthreads();
    float aq = bq[t], ak = bk[t];
    #pragma unroll
    for (int c = 0; c < DS; c++) {
        float s = st[c];
        aq += s * Wq[c * 128 + t];
        ak += s * Wk[c * 128 + t];
    }
    g_q[l * 128 + t] = aq;
    g_k[l * 128 + t] = ak;
}

// =====================================================================
// K2 (fused): blocks [0,1024) = v path; blocks [1024,3072) = attn softmax.
// =====================================================================
__global__ void __launch_bounds__(256) prep_kernel(
        const float* __restrict__ Ca,
        const float* __restrict__ msa,
        const float* __restrict__ n1g, const float* __restrict__ n1b,
        const float* __restrict__ Wv, const float* __restrict__ bv) {
    __shared__ float Wvp[4096];
    __shared__ float Ap[4096];
    __shared__ float sbv[DM], sg[DM], sb[DM];
    __shared__ float qv[DK];
    __shared__ float red[8];
    __shared__ float cai[3];

    int t = threadIdx.x;

    if (blockIdx.x < 1024) {
        int warp = t >> 5, lane = t & 31;
        int rg = lane >> 2, q2 = (lane & 3) * 2;
        for (int i = t; i < 4096; i += 256) {
            int c = i >> 6, n = i & 63;
            Wvp[bfrag_addr(c, n, 8)] = Wv[i];
        }
        if (t < DM) { sbv[t] = bv[t]; sg[t] = n1g[t]; sb[t] = n1b[t]; }
        __syncthreads();

        int wm = warp >> 2, wn = warp & 3;
        for (int tile = blockIdx.x; tile < NROWS / 64; tile += 1024) {
            size_t row0 = (size_t)tile * 64;
            #pragma unroll
            for (int rr = 0; rr < 8; rr++) {
                int row = warp * 8 + rr;
                float2 x2 = *(const float2*)&msa[(row0 + row) * DM + 2 * lane];
                float sum = x2.x + x2.y;
                #pragma unroll
                for (int o = 16; o; o >>= 1) sum += __shfl_xor_sync(0xffffffffu, sum, o);
                float m = sum * (1.0f / DM);
                float d0 = x2.x - m, d1 = x2.y - m;
                float vv = d0 * d0 + d1 * d1;
                #pragma unroll
                for (int o = 16; o; o >>= 1) vv += __shfl_xor_sync(0xffffffffu, vv, o);
                float r = rsqrtf(vv * (1.0f / DM) + EPSLN);
                int c0 = 2 * lane;
                Ap[afrag_addr(row, c0, 8)]     = d0 * r * sg[c0]     + sb[c0];
                Ap[afrag_addr(row, c0 + 1, 8)] = d1 * r * sg[c0 + 1] + sb[c0 + 1];
            }
            __syncthreads();
            float acc[2][2][4];
            #pragma unroll
            for (int x = 0; x < 2; x++)
                #pragma unroll
                for (int y = 0; y < 2; y++)
                    #pragma unroll
                    for (int r = 0; r < 4; r++) acc[x][y][r] = 0.0f;
            #pragma unroll
            for (int ks = 0; ks < 8; ks++) {
                float4 af[2];
                float2 bf[2];
                #pragma unroll
                for (int mt = 0; mt < 2; mt++)
                    af[mt] = *(const float4*)&Ap[((wm * 2 + mt) * 8 + ks) * 128 + lane * 4];
                #pragma unroll
                for (int nt = 0; nt < 2; nt++)
                    bf[nt] = *(const float2*)&Wvp[((wn * 2 + nt) * 8 + ks) * 64 + lane * 2];
                #pragma unroll
                for (int mt = 0; mt < 2; mt++)
                    #pragma unroll
                    for (int nt = 0; nt < 2; nt++)
                        mma_tf32(acc[mt][nt][0], acc[mt][nt][1], acc[mt][nt][2], acc[mt][nt][3],
                                 F2U(af[mt].x), F2U(af[mt].y), F2U(af[mt].z), F2U(af[mt].w),
                                 F2U(bf[nt].x), F2U(bf[nt].y));
            }
            __syncthreads();
            #pragma unroll
            for (int mt = 0; mt < 2; mt++) {
                #pragma unroll
                for (int nt = 0; nt < 2; nt++) {
                    int rt0 = wm * 32 + mt * 16 + rg;
                    int c0 = wn * 16 + nt * 8 + q2;
                    #pragma unroll
                    for (int e = 0; e < 4; e++) {
                        int rt = rt0 + (e >> 1) * 8;
                        int cc = c0 + (e & 1);
                        int h = cc >> 4, d = cc & 15;
                        int sidx = ((((h * 2 + (rt >> 5)) * 2 + (d >> 3)) * 4)
                                    + ((rt >> 3) & 3)) * 64
                                 + (d & 7) * 8 + (rt & 3) * 2 + ((rt >> 2) & 1);
                        Ap[sidx] = acc[mt][nt][e] + sbv[cc];
                    }
                }
            }
            __syncthreads();
            {
                int n = (int)(row0 >> 9);
                int j0s = (int)((row0 & 511) >> 5);
                int blk = n >> 3;
                #pragma unroll
                for (int u = 0; u < 4; u++) {
                    int f = t + u * 256;
                    int b = f >> 4;
                    int off = (f & 15) * 4;
                    int h = b >> 4, kcl = (b >> 3) & 1, dhi = (b >> 2) & 1, krhi = b & 3;
                    size_t dst = ((size_t)(h * 32 + blk) * 16 + j0s + kcl) * 4096
                               + (size_t)((((n & 7) * 2 + dhi) * 4 + krhi) * 64 + off);
                    *(float4*)&g_vT[dst] = *(const float4*)&Ap[b * 64 + off];
                }
            }
            __syncthreads();
        }
    } else {
        int idx = blockIdx.x - 1024;
        int i = idx & 511, h = idx >> 9;
        if (t < DK) qv[t] = g_q[i * 128 + h * DK + t];
        if (t < 3)  cai[t] = Ca[i * 3 + t];
        __syncthreads();

        float bin = (float)(4 * (h + 1)) / 10.0f;
        float bin2 = bin * bin;
        const float scaling = 0.17677669529663687f;
        float cx = cai[0], cy = cai[1], cz = cai[2];

        float sc[2];
        #pragma unroll
        for (int u = 0; u < 2; u++) {
            int j = t + u * 256;
            float dx = Ca[3 * j] - cx, dy = Ca[3 * j + 1] - cy, dz = Ca[3 * j + 2] - cz;
            float sq = fmaxf(dx * dx + dy * dy + dz * dz, 1e-12f);
            if (sq > bin2) {
                sc[u] = NEGMAX;
            } else {
                float a = 0.0f;
                const float* kp = &g_k[j * 128 + h * DK];
                #pragma unroll
                for (int d = 0; d < DK; d++) a += qv[d] * kp[d];
                sc[u] = a * scaling;
            }
        }
        float mx = fmaxf(sc[0], sc[1]);
        #pragma unroll
        for (int o = 16; o; o >>= 1) mx = fmaxf(mx, __shfl_xor_sync(0xffffffffu, mx, o));
        if ((t & 31) == 0) red[t >> 5] = mx;
        __syncthreads();
        mx = red[0];
        #pragma unroll
        for (int w = 1; w < 8; w++) mx = fmaxf(mx, red[w]);

        float e0 = expf(sc[0] - mx);
        float e1 = expf(sc[1] - mx);
        float ss = e0 + e1;
        #pragma unroll
        for (int o = 16; o; o >>= 1) ss += __shfl_xor_sync(0xffffffffu, ss, o);
        __syncthreads();
        if ((t & 31) == 0) red[t >> 5] = ss;
        __syncthreads();
        ss = red[0];
        #pragma unroll
        for (int w = 1; w < 8; w++) ss += red[w];
        float inv = 1.0f / ss;

        int iblk = i >> 7, ib = i & 127;
        size_t blkbase = ((size_t)(h * 4 + iblk) * 16) * 4096;
        float vals[2] = {e0 * inv, e1 * inv};
        #pragma unroll
        for (int u = 0; u < 2; u++) {
            int j = t + u * 256;
            int kc = j >> 5;
            g_attn[blkbase + (size_t)kc * 4096 + afrag_addr(ib, j & 31, 4)] = vals[u];
        }
    }
}

// =====================================================================
// K3 (mma tf32 + cp.async 3-stage): per-head C = attn @ vT.  grid=(32,4,4)
// =====================================================================
extern __shared__ float gsh[];
__global__ void __launch_bounds__(256, 2) gemm_attn_mma() {
    int h  = blockIdx.z;
    const float* __restrict__ Abase =
        g_attn + ((size_t)(h * 4 + blockIdx.y) * 16) * 4096;
    const float* __restrict__ Bbase =
        g_vT + ((size_t)(h * 32 + blockIdx.x) * 16) * 4096;

    float* sA = gsh;
    float* sB = gsh + 12288;

    int t = threadIdx.x, wid = t >> 5, lid = t & 31;
    int wm = wid >> 2, wn = wid & 3;
    uint32_t aAddr = smem_u32(sA) + t * 16;
    uint32_t bAddr = smem_u32(sB) + t * 16;

    float acc[4][4][4];
    #pragma unroll
    for (int x = 0; x < 4; x++)
        #pragma unroll
        for (int y = 0; y < 4; y++)
            #pragma unroll
            for (int r = 0; r < 4; r++) acc[x][y][r] = 0.0f;

    #pragma unroll 1
    for (int p = 0; p < 2; p++) {
        const float4* srcA = (const float4*)(Abase + (size_t)p * 4096) + t;
        const float4* srcB = (const float4*)(Bbase + (size_t)p * 4096) + t;
        #pragma unroll
        for (int u = 0; u < 4; u++) {
            cp16(aAddr + p * 16384 + u * 4096, srcA + u * 256);
            cp16(bAddr + p * 16384 + u * 4096, srcB + u * 256);
        }
        CP_COMMIT();
    }

    #pragma unroll 1
    for (int kc = 0; kc < 16; kc++) {
        if (kc + 2 < 16) {
            int st = (kc + 2) % 3;
            const float4* srcA = (const float4*)(Abase + (size_t)(kc + 2) * 4096) + t;
            const float4* srcB = (const float4*)(Bbase + (size_t)(kc + 2) * 4096) + t;
            #pragma unroll
            for (int u = 0; u < 4; u++) {
                cp16(aAddr + st * 16384 + u * 4096, srcA + u * 256);
                cp16(bAddr + st * 16384 + u * 4096, srcB + u * 256);
            }
        }
        CP_COMMIT();
        CP_WAIT2();
        __syncthreads();
        const float* cA = sA + (kc % 3) * 4096;
        const float* cB = sB + (kc % 3) * 4096;
        #pragma unroll
        for (int ks = 0; ks < 4; ks++) {
            uint32_t bf[4][2];
            #pragma unroll
            for (int nt2 = 0; nt2 < 4; nt2++) {
                int nt = wn * 4 + nt2;
                float2 b2 = *(const float2*)&cB[(nt * 4 + ks) * 64 + lid * 2];
                bf[nt2][0] = F2U(b2.x);
                bf[nt2][1] = F2U(b2.y);
            }
            #pragma unroll
            for (int mt2 = 0; mt2 < 4; mt2++) {
                int mt = wm * 4 + mt2;
                float4 a4 = *(const float4*)&cA[(mt * 4 + ks) * 128 + lid * 4];
                #pragma unroll
                for (int nt2 = 0; nt2 < 4; nt2++)
                    mma_tf32(acc[mt2][nt2][0], acc[mt2][nt2][1],
                             acc[mt2][nt2][2], acc[mt2][nt2][3],
                             F2U(a4.x), F2U(a4.y), F2U(a4.z), F2U(a4.w),
                             bf[nt2][0], bf[nt2][1]);
            }
        }
        __syncthreads();
    }

    float* stg = gsh;
    int rg = lid >> 2, q2 = (lid & 3) * 2;
    #pragma unroll
    for (int mt2 = 0; mt2 < 4; mt2++) {
        #pragma unroll
        for (int nt2 = 0; nt2 < 4; nt2++) {
            int nloc = wn * 2 + (nt2 >> 1);
            #pragma unroll
            for (int e = 0; e < 4; e++) {
                int rt = mt2 * 16 + rg + (e >> 1) * 8;
                int d = (nt2 & 1) * 8 + q2 + (e & 1);
                int sidx = (((wm * 8 + nloc) * 2 + (d >> 3)) * 4 + mt2) * 128
                         + (rt & 7) * 16 + ((rt >> 3) & 1)
                         + (d & 3) * 4 + ((d >> 2) & 1) * 2;
                stg[sidx] = acc[mt2][nt2][e];
            }
        }
    }
    __syncthreads();
    #pragma unroll
    for (int u = 0; u < 16; u++) {
        int f = t + u * 256;
        int b = f >> 5;
        int off = (f & 31) * 4;
        int krt = b & 3, dhi = (b >> 2) & 1, nloc = (b >> 3) & 7, iloc = b >> 6;
        int n = blockIdx.x * 8 + nloc;
        size_t rtile = (size_t)n * 8 + blockIdx.y * 2 + iloc;
        size_t dst = rtile * 4096 + (size_t)((krt * 8 + h * 2 + dhi) * 128 + off);
        *(float4*)&g_attout[dst] = *(const float4*)&stg[b * 128 + off];
    }
}

// =====================================================================
// K5 (mma tf32): msax = msa + attout@Wo + bo.  grid=1024, 2 tiles/CTA,
// double-buffered cp.async Ap load.  dyn smem: Wop[4096] + Ap[2][4096].
// =====================================================================
__global__ void __launch_bounds__(256) oproj_mma_kernel(
        const float* __restrict__ msa,
        const float* __restrict__ Wo, const float* __restrict__ bo) {
    float* Wop = gsh;                 // [4096]
    float* Apb = gsh + 4096;          // [2][4096]
    __shared__ float sbo[DM];
    int t = threadIdx.x, warp = t >> 5, lane = t & 31;
    int rg = lane >> 2, q2 = (lane & 3) * 2;
    int wm = warp >> 2, wn = warp & 3;
    uint32_t apAddr = smem_u32(Apb) + t * 16;

    // prologue: async-load first tile while permuting weights
    {
        const float4* src = (const float4*)(g_attout + (size_t)blockIdx.x * 4096) + t;
        #pragma unroll
        for (int u = 0; u < 4; u++)
            cp16(apAddr + u * 4096, src + u * 256);
        CP_COMMIT();
    }
    for (int i = t; i < 4096; i += 256) {
        int c = i >> 6, n = i & 63;
        Wop[bfrag_addr(c, n, 8)] = Wo[i];
    }
    if (t < DM) sbo[t] = bo[t];

    int buf = 0;
    for (int tile = blockIdx.x; tile < NROWS / 64; tile += gridDim.x) {
        int nxt = tile + gridDim.x;
        if (nxt < NROWS / 64) {
            const float4* src = (const float4*)(g_attout + (size_t)nxt * 4096) + t;
            #pragma unroll
            for (int u = 0; u < 4; u++)
                cp16(apAddr + (buf ^ 1) * 16384 + u * 4096, src + u * 256);
        }
        CP_COMMIT();
        CP_WAIT1();
        __syncthreads();
        const float* cAp = Apb + buf * 4096;
        size_t row0 = (size_t)tile * 64;

        float acc[2][2][4];
        #pragma unroll
        for (int x = 0; x < 2; x++)
            #pragma unroll
            for (int y = 0; y < 2; y++)
                #pragma unroll
                for (int r = 0; r < 4; r++) acc[x][y][r] = 0.0f;
        #pragma unroll
        for (int ks = 0; ks < 8; ks++) {
            float4 af[2];
            float2 bf[2];
            #pragma unroll
            for (int mt = 0; mt < 2; mt++)
                af[mt] = *(const float4*)&cAp[((wm * 2 + mt) * 8 + ks) * 128 + lane * 4];
            #pragma unroll
            for (int nt = 0; nt < 2; nt++)
                bf[nt] = *(const float2*)&Wop[((wn * 2 + nt) * 8 + ks) * 64 + lane * 2];
            #pragma unroll
            for (int mt = 0; mt < 2; mt++)
                #pragma unroll
                for (int nt = 0; nt < 2; nt++)
                    mma_tf32(acc[mt][nt][0], acc[mt][nt][1], acc[mt][nt][2], acc[mt][nt][3],
                             F2U(af[mt].x), F2U(af[mt].y), F2U(af[mt].z), F2U(af[mt].w),
                             F2U(bf[nt].x), F2U(bf[nt].y));
        }
        #pragma unroll
        for (int mt = 0; mt < 2; mt++) {
            #pragma unroll
            for (int nt = 0; nt < 2; nt++) {
                int rt0 = wm * 32 + mt * 16 + rg;
                int c0 = wn * 16 + nt * 8 + q2;
                float bo0 = sbo[c0], bo1 = sbo[c0 + 1];
                #pragma unroll
                for (int half = 0; half < 2; half++) {
                    size_t r = row0 + rt0 + half * 8;
                    float2 m2 = *(const float2*)&msa[r * DM + c0];
                    *(float2*)&g_msax[r * DM + c0] =
                        make_float2(acc[mt][nt][half * 2]     + bo0 + m2.x,
                                    acc[mt][nt][half * 2 + 1] + bo1 + m2.y);
                }
            }
        }
        __syncthreads();     // all reads of Ap[buf] done before it is refilled
        buf ^= 1;
    }
}

// =====================================================================
// K6 (mma tf32, 512 threads): fused FF + final LN.
// 16 warps: GEMM1 2m x 8n; GEMM2 2m x 2n x 4k-split (partials in Ps).
// =====================================================================
struct FFS4 {
    float W1p[DM * FFH];
    float W2p[FFH * DM];
    float b1s[FFH];
    float b2s[DM], g2[DM], bn2[DM], g3[DM], bn3[DM];
    float Xs[64 * DM];
    float Ap[64 * DM];
    float Hp[64 * FFH];
};
extern __shared__ unsigned char ff_raw[];

__global__ void __launch_bounds__(512) ff_mma_kernel(
        const float* __restrict__ n2g, const float* __restrict__ n2b,
        const float* __restrict__ W1, const float* __restrict__ b1,
        const float* __restrict__ W2, const float* __restrict__ b2,
        const float* __restrict__ n3g, const float* __restrict__ n3b,
        float* __restrict__ out) {
    FFS4* s = (FFS4*)ff_raw;
    int t = threadIdx.x, warp = t >> 5, lane = t & 31;
    int rg = lane >> 2, q2 = (lane & 3) * 2;

    for (int i = t; i < DM * FFH; i += 512) {
        int c = i >> 8, n = i & 255;
        s->W1p[bfrag_addr(c, n, 8)] = W1[i];
    }
    for (int i = t; i < FFH * DM; i += 512) {
        int c = i >> 6, n = i & 63;
        s->W2p[bfrag_addr(c, n, 32)] = W2[i];
    }
    if (t < FFH) s->b1s[t] = b1[t];
    if (t < DM) { s->b2s[t] = b2[t]; s->g2[t] = n2g[t]; s->bn2[t] = n2b[t];
                  s->g3[t] = n3g[t]; s->bn3[t] = n3b[t]; }
    __syncthreads();

    const int nTiles = NROWS / 64;
    float4 xr[2];
    if (blockIdx.x < nTiles) {
        const float4* src = (const float4*)&g_msax[(size_t)blockIdx.x * 4096];
        #pragma unroll
        for (int i = 0; i < 2; i++) xr[i] = src[t * 2 + i];
    }

    for (int tile = blockIdx.x; tile < nTiles; tile += gridDim.x) {
        size_t row0 = (size_t)tile * 64;
        #pragma unroll
        for (int i = 0; i < 2; i++)
            *(float4*)&s->Xs[(t * 2 + i) * 4] = xr[i];
        __syncthreads();
        int nxt = tile + gridDim.x;
        if (nxt < nTiles) {
            const float4* src = (const float4*)&g_msax[(size_t)nxt * 4096];
            #pragma unroll
            for (int i = 0; i < 2; i++) xr[i] = src[t * 2 + i];
        }
        #pragma unroll
        for (int rr = 0; rr < 4; rr++) {
            int row = warp * 4 + rr;
            float2 x2 = *(const float2*)&s->Xs[row * DM + 2 * lane];
            float sum = x2.x + x2.y;
            #pragma unroll
            for (int o = 16; o; o >>= 1) sum += __shfl_xor_sync(0xffffffffu, sum, o);
            float m = sum * (1.0f / DM);
            float d0 = x2.x - m, d1 = x2.y - m;
            float vv = d0 * d0 + d1 * d1;
            #pragma unroll
            for (int o = 16; o; o >>= 1) vv += __shfl_xor_sync(0xffffffffu, vv, o);
            float r = rsqrtf(vv * (1.0f / DM) + EPSLN);
            int c0 = 2 * lane;
            s->Ap[afrag_addr(row, c0, 8)]     = d0 * r * s->g2[c0]     + s->bn2[c0];
            s->Ap[afrag_addr(row, c0 + 1, 8)] = d1 * r * s->g2[c0 + 1] + s->bn2[c0 + 1];
        }
        __syncthreads();
        {
            int wm = warp >> 3, wn = warp & 7;
            float acc1[2][4][4];
            #pragma unroll
            for (int x = 0; x < 2; x++)
                #pragma unroll
                for (int y = 0; y < 4; y++)
                    #pragma unroll
                    for (int r = 0; r < 4; r++) acc1[x][y][r] = 0.0f;
            #pragma unroll
            for (int ks = 0; ks < 8; ks++) {
                float4 af0 = *(const float4*)&s->Ap[((wm * 2 + 0) * 8 + ks) * 128 + lane * 4];
                float4 af1 = *(const float4*)&s->Ap[((wm * 2 + 1) * 8 + ks) * 128 + lane * 4];
                #pragma unroll
                for (int nt = 0; nt < 4; nt++) {
                    float2 b2v = *(const float2*)&s->W1p[((wn * 4 + nt) * 8 + ks) * 64 + lane * 2];
                    mma_tf32(acc1[0][nt][0], acc1[0][nt][1], acc1[0][nt][2], acc1[0][nt][3],
                             F2U(af0.x), F2U(af0.y), F2U(af0.z), F2U(af0.w),
                             F2U(b2v.x), F2U(b2v.y));
                    mma_tf32(acc1[1][nt][0], acc1[1][nt][1], acc1[1][nt][2], acc1[1][nt][3],
                             F2U(af1.x), F2U(af1.y), F2U(af1.z), F2U(af1.w),
                             F2U(b2v.x), F2U(b2v.y));
                }
            }
            #pragma unroll
            for (int mt = 0; mt < 2; mt++) {
                int mtg = wm * 2 + mt;
                #pragma unroll
                for (int nt = 0; nt < 4; nt++) {
                    int ks2 = wn * 4 + nt;
                    int c0 = ks2 * 8 + q2;
                    float b1a = s->b1s[c0], b1b = s->b1s[c0 + 1];
                    float v0 = fmaxf(acc1[mt][nt][0] + b1a, 0.f);
                    float v1 = fmaxf(acc1[mt][nt][1] + b1b, 0.f);
                    float v2 = fmaxf(acc1[mt][nt][2] + b1a, 0.f);
                    float v3 = fmaxf(acc1[mt][nt][3] + b1b, 0.f);
                    int fb = (mtg * 32 + ks2) * 128 + rg * 16;
                    int a0 = fb + (q2 & 3) * 4 + ((q2 >> 2) << 1);
                    int kk1 = q2 + 1;
                    int a1 = fb + (kk1 & 3) * 4 + ((kk1 >> 2) << 1);
                    *(float2*)&s->Hp[a0] = make_float2(v0, v2);
                    *(float2*)&s->Hp[a1] = make_float2(v1, v3);
                }
            }
        }
        __syncthreads();
        {
            int kg = warp >> 2;
            int wm2 = (warp >> 1) & 1, wn2 = warp & 1;
            float acc2[2][4][4];
            #pragma unroll
            for (int x = 0; x < 2; x++)
                #pragma unroll
                for (int y = 0; y < 4; y++)
                    #pragma unroll
                    for (int r = 0; r < 4; r++) acc2[x][y][r] = 0.0f;
            #pragma unroll
            for (int ks = 0; ks < 8; ks++) {
                int ksg = kg * 8 + ks;
                float4 af0 = *(const float4*)&s->Hp[((wm2 * 2 + 0) * 32 + ksg) * 128 + lane * 4];
                float4 af1 = *(const float4*)&s->Hp[((wm2 * 2 + 1) * 32 + ksg) * 128 + lane * 4];
                #pragma unroll
                for (int nt = 0; nt < 4; nt++) {
                    float2 b2v = *(const float2*)&s->W2p[((wn2 * 4 + nt) * 32 + ksg) * 64 + lane * 2];
                    mma_tf32(acc2[0][nt][0], acc2[0][nt][1], acc2[0][nt][2], acc2[0][nt][3],
                             F2U(af0.x), F2U(af0.y), F2U(af0.z), F2U(af0.w),
                             F2U(b2v.x), F2U(b2v.y));
                    mma_tf32(acc2[1][nt][0], acc2[1][nt][1], acc2[1][nt][2], acc2[1][nt][3],
                             F2U(af1.x), F2U(af1.y), F2U(af1.z), F2U(af1.w),
                             F2U(b2v.x), F2U(b2v.y));
                }
            }
            __syncthreads();
            float* Ps = s->Ap;
            #pragma unroll
            for (int mt = 0; mt < 2; mt++)
                #pragma unroll
                for (int nt = 0; nt < 4; nt++) {
                    int r0 = wm2 * 32 + mt * 16 + rg;
                    int c0 = wn2 * 32 + nt * 8 + q2;
                    *(float2*)&Ps[kg * 4608 + r0 * 72 + c0] =
                        make_float2(acc2[mt][nt][0], acc2[mt][nt][1]);
                    *(float2*)&Ps[kg * 4608 + (r0 + 8) * 72 + c0] =
                        make_float2(acc2[mt][nt][2], acc2[mt][nt][3]);
                }
        }
        __syncthreads();
        {
            float* Ps = s->Ap;
            int row = t >> 3, c0 = (t & 7) * 8;
            #pragma unroll
            for (int i = 0; i < 2; i++) {
                int c = c0 + i * 4;
                float4 xv = *(const float4*)&s->Xs[row * DM + c];
                float4 bv = *(const float4*)&s->b2s[c];
                float4 p0 = *(const float4*)&Ps[row * 72 + c];
                float4 p1 = *(const float4*)&Ps[4608 + row * 72 + c];
                float4 p2 = *(const float4*)&Ps[9216 + row * 72 + c];
                float4 p3 = *(const float4*)&Ps[13824 + row * 72 + c];
                *(float4*)&s->Xs[row * DM + c] =
                    make_float4(xv.x + bv.x + p0.x + p1.x + p2.x + p3.x,
                                xv.y + bv.y + p0.y + p1.y + p2.y + p3.y,
                                xv.z + bv.z + p0.z + p1.z + p2.z + p3.z,
                                xv.w + bv.w + p0.w + p1.w + p2.w + p3.w);
            }
        }
        __syncthreads();
        #pragma unroll
        for (int rr = 0; rr < 4; rr++) {
            int row = warp * 4 + rr;
            float2 y2 = *(const float2*)&s->Xs[row * DM + 2 * lane];
            float sum = y2.x + y2.y;
            #pragma unroll
            for (int o = 16; o; o >>= 1) sum += __shfl_xor_sync(0xffffffffu, sum, o);
            float m = sum * (1.0f / DM);
            float d0 = y2.x - m, d1 = y2.y - m;
            float vv = d0 * d0 + d1 * d1;
            #pragma unroll
            for (int o = 16; o; o >>= 1) vv += __shfl_xor_sync(0xffffffffu, vv, o);
            float r = rsqrtf(vv * (1.0f / DM) + EPSLN);
            size_t ob = (row0 + row) * DM;
            out[ob + 2 * lane]     = d0 * r * s->g3[2 * lane]     + s->bn3[2 * lane];
            out[ob + 2 * lane + 1] = d1 * r * s->g3[2 * lane + 1] + s->bn3[2 * lane + 1];
        }
        __syncthreads();
    }
}

// =====================================================================
extern "C" void kernel_launch(void* const* d_in, const int* in_sizes, int n_in,
                              void* d_out, int out_size) {
    const float* msa   = (const float*)d_in[0];
    const float* Ca    = (const float*)d_in[1];
    const float* state = (const float*)d_in[2];
    const float* ns_g  = (const float*)d_in[3];
    const float* ns_b  = (const float*)d_in[4];
    const float* n1_g  = (const float*)d_in[5];
    const float* n1_b  = (const float*)d_in[6];
    const float* Wq    = (const float*)d_in[7];
    const float* bq    = (const float*)d_in[8];
    const float* Wk    = (const float*)d_in[9];
    const float* bk    = (const float*)d_in[10];
    const float* Wv    = (const float*)d_in[11];
    const float* bv    = (const float*)d_in[12];
    const float* Wo    = (const float*)d_in[13];
    const float* bo    = (const float*)d_in[14];
    const float* n2_g  = (const float*)d_in[15];
    const float* n2_b  = (const float*)d_in[16];
    const float* W1    = (const float*)d_in[17];
    const float* b1    = (const float*)d_in[18];
    const float* W2    = (const float*)d_in[19];
    const float* b2    = (const float*)d_in[20];
    const float* n3_g  = (const float*)d_in[21];
    const float* n3_b  = (const float*)d_in[22];
    float* out = (float*)d_out;

    cudaFuncSetAttribute(ff_mma_kernel, cudaFuncAttributeMaxDynamicSharedMemorySize,
                         (int)sizeof(FFS4));
    cudaFuncSetAttribute(gemm_attn_mma, cudaFuncAttributeMaxDynamicSharedMemorySize,
                         98304);
    cudaFuncSetAttribute(oproj_mma_kernel, cudaFuncAttributeMaxDynamicSharedMemorySize,
                         49152);

    qk_kernel<<<L, 128>>>(state, ns_g, ns_b, Wq, bq, Wk, bk);
    prep_kernel<<<3072, 256>>>(Ca, msa, n1_g, n1_b, Wv, bv);
    gemm_attn_mma<<<dim3(32, 4, 4), 256, 98304>>>();
    oproj_mma_kernel<<<1024, 256, 49152>>>(msa, Wo, bo);
    ff_mma_kernel<<<148, 512, sizeof(FFS4)>>>(n2_g, n2_b, W1, b1, W2, b2, n3_g, n3_b, out);
}

// round 15
// speedup vs baseline: 1.0631x; 1.0157x over previous
#include <cuda_runtime.h>
#include <cuda_bf16.h>
#include <math.h>
#include <stdint.h>

// ---------------- problem constants ----------------
#define L 512
#define NSEQ 256
#define DM 64
#define DS 32
#define NH 4
#define DK 32
#define DV 16
#define FFH 256
#define NROWS (NSEQ * L)
#define EPSLN 1e-5f
#define NEGMAX (-3.402823466e38f)

// ---------------- scratch ----------------
__device__ float g_q[L * NH * DK];
__device__ float g_k[L * NH * DK];
__device__ float g_attn[NH * L * L];          // A-frag: [h][iblk(4)][kc(16)][4096]
__device__ float g_vT[NH * L * NSEQ * DV];    // B-frag: [h][nblk(32)][kc(16)][4096]
__device__ float g_attout[NROWS * DM];        // A-frag 64-row tiles: [tile][4096]
__device__ float g_msax[NROWS * DM];          // raw rows

__device__ __forceinline__ void mma_tf32(float& c0, float& c1, float& c2, float& c3,
                                         uint32_t a0, uint32_t a1, uint32_t a2, uint32_t a3,
                                         uint32_t b0, uint32_t b1) {
    asm volatile(
        "mma.sync.aligned.m16n8k8.row.col.f32.tf32.tf32.f32 "
        "{%0,%1,%2,%3}, {%4,%5,%6,%7}, {%8,%9}, {%0,%1,%2,%3};"
        : "+f"(c0), "+f"(c1), "+f"(c2), "+f"(c3)
        : "r"(a0), "r"(a1), "r"(a2), "r"(a3), "r"(b0), "r"(b1));
}
#define F2U(x) __float_as_uint(x)

__device__ __forceinline__ uint32_t smem_u32(const void* p) {
    uint32_t a;
    asm("{ .reg .u64 tmp; cvta.to.shared.u64 tmp, %1; cvt.u32.u64 %0, tmp; }"
        : "=r"(a) : "l"(p));
    return a;
}
__device__ __forceinline__ void cp16(uint32_t smem, const void* gmem) {
    asm volatile("cp.async.cg.shared.global [%0], [%1], 16;" :: "r"(smem), "l"(gmem));
}
#define CP_COMMIT() asm volatile("cp.async.commit_group;")
#define CP_WAIT2()  asm volatile("cp.async.wait_group 2;")
#define CP_WAIT1()  asm volatile("cp.async.wait_group 1;")

__device__ __forceinline__ int afrag_addr(int r, int c, int KS8) {
    return ((r >> 4) * KS8 + (c >> 3)) * 128 + (r & 7) * 16 + ((r >> 3) & 1)
         + (c & 3) * 4 + ((c >> 2) & 1) * 2;
}
__device__ __forceinline__ int bfrag_addr(int c, int n, int KS8) {
    return ((n >> 3) * KS8 + (c >> 3)) * 64 + (n & 7) * 8 + (c & 3) * 2 + ((c >> 2) & 1);
}

// =====================================================================
// K1: st = LN(state); q,k projections.  grid=512, block=128
// =====================================================================
__global__ void qk_kernel(const float* __restrict__ state,
                          const float* __restrict__ nsg, const float* __restrict__ nsb,
                          const float* __restrict__ Wq, const float* __restrict__ bq,
                          const float* __restrict__ Wk, const float* __restrict__ bk) {
    int l = blockIdx.x;
    int t = threadIdx.x;
    __shared__ float st[DS];
    if (t < DS) {
        float x = state[l * DS + t];
        float s = x;
        #pragma unroll
        for (int o = 16; o; o >>= 1) s += __shfl_xor_sync(0xffffffffu, s, o);
        float m = s * (1.0f / DS);
        float d = x - m;
        float v = d * d;
        #pragma unroll
        for (int o = 16; o; o >>= 1) v += __shfl_xor_sync(0xffffffffu, v, o);
        float r = rsqrtf(v * (1.0f / DS) + EPSLN);
        st[t] = d * r * nsg[t] + nsb[t];
    }
    __syncthreads();
    float aq = bq[t], ak = bk[t];
    #pragma unroll
    for (int c = 0; c < DS; c++) {
        float s = st[c];
        aq += s * Wq[c * 128 + t];
        ak += s * Wk[c * 128 + t];
    }
    g_q[l * 128 + t] = aq;
    g_k[l * 128 + t] = ak;
}

// =====================================================================
// K2 (fused): blocks [0,1024) = v path; blocks [1024,3072) = attn softmax.
// =====================================================================
__global__ void __launch_bounds__(256) prep_kernel(
        const float* __restrict__ Ca,
        const float* __restrict__ msa,
        const float* __restrict__ n1g, const float* __restrict__ n1b,
        const float* __restrict__ Wv, const float* __restrict__ bv) {
    __shared__ float Wvp[4096];
    __shared__ float Ap[4096];
    __shared__ float sbv[DM], sg[DM], sb[DM];
    __shared__ float qv[DK];
    __shared__ float red[8];
    __shared__ float cai[3];

    int t = threadIdx.x;

    if (blockIdx.x < 1024) {
        int warp = t >> 5, lane = t & 31;
        int rg = lane >> 2, q2 = (lane & 3) * 2;
        for (int i = t; i < 4096; i += 256) {
            int c = i >> 6, n = i & 63;
            Wvp[bfrag_addr(c, n, 8)] = Wv[i];
        }
        if (t < DM) { sbv[t] = bv[t]; sg[t] = n1g[t]; sb[t] = n1b[t]; }
        __syncthreads();

        int wm = warp >> 2, wn = warp & 3;
        for (int tile = blockIdx.x; tile < NROWS / 64; tile += 1024) {
            size_t row0 = (size_t)tile * 64;
            #pragma unroll
            for (int rr = 0; rr < 8; rr++) {
                int row = warp * 8 + rr;
                float2 x2 = *(const float2*)&msa[(row0 + row) * DM + 2 * lane];
                float sum = x2.x + x2.y;
                #pragma unroll
                for (int o = 16; o; o >>= 1) sum += __shfl_xor_sync(0xffffffffu, sum, o);
                float m = sum * (1.0f / DM);
                float d0 = x2.x - m, d1 = x2.y - m;
                float vv = d0 * d0 + d1 * d1;
                #pragma unroll
                for (int o = 16; o; o >>= 1) vv += __shfl_xor_sync(0xffffffffu, vv, o);
                float r = rsqrtf(vv * (1.0f / DM) + EPSLN);
                int c0 = 2 * lane;
                Ap[afrag_addr(row, c0, 8)]     = d0 * r * sg[c0]     + sb[c0];
                Ap[afrag_addr(row, c0 + 1, 8)] = d1 * r * sg[c0 + 1] + sb[c0 + 1];
            }
            __syncthreads();
            float acc[2][2][4];
            #pragma unroll
            for (int x = 0; x < 2; x++)
                #pragma unroll
                for (int y = 0; y < 2; y++)
                    #pragma unroll
                    for (int r = 0; r < 4; r++) acc[x][y][r] = 0.0f;
            #pragma unroll
            for (int ks = 0; ks < 8; ks++) {
                float4 af[2];
                float2 bf[2];
                #pragma unroll
                for (int mt = 0; mt < 2; mt++)
                    af[mt] = *(const float4*)&Ap[((wm * 2 + mt) * 8 + ks) * 128 + lane * 4];
                #pragma unroll
                for (int nt = 0; nt < 2; nt++)
                    bf[nt] = *(const float2*)&Wvp[((wn * 2 + nt) * 8 + ks) * 64 + lane * 2];
                #pragma unroll
                for (int mt = 0; mt < 2; mt++)
                    #pragma unroll
                    for (int nt = 0; nt < 2; nt++)
                        mma_tf32(acc[mt][nt][0], acc[mt][nt][1], acc[mt][nt][2], acc[mt][nt][3],
                                 F2U(af[mt].x), F2U(af[mt].y), F2U(af[mt].z), F2U(af[mt].w),
                                 F2U(bf[nt].x), F2U(bf[nt].y));
            }
            __syncthreads();
            #pragma unroll
            for (int mt = 0; mt < 2; mt++) {
                #pragma unroll
                for (int nt = 0; nt < 2; nt++) {
                    int rt0 = wm * 32 + mt * 16 + rg;
                    int c0 = wn * 16 + nt * 8 + q2;
                    #pragma unroll
                    for (int e = 0; e < 4; e++) {
                        int rt = rt0 + (e >> 1) * 8;
                        int cc = c0 + (e & 1);
                        int h = cc >> 4, d = cc & 15;
                        int sidx = ((((h * 2 + (rt >> 5)) * 2 + (d >> 3)) * 4)
                                    + ((rt >> 3) & 3)) * 64
                                 + (d & 7) * 8 + (rt & 3) * 2 + ((rt >> 2) & 1);
                        Ap[sidx] = acc[mt][nt][e] + sbv[cc];
                    }
                }
            }
            __syncthreads();
            {
                int n = (int)(row0 >> 9);
                int j0s = (int)((row0 & 511) >> 5);
                int blk = n >> 3;
                #pragma unroll
                for (int u = 0; u < 4; u++) {
                    int f = t + u * 256;
                    int b = f >> 4;
                    int off = (f & 15) * 4;
                    int h = b >> 4, kcl = (b >> 3) & 1, dhi = (b >> 2) & 1, krhi = b & 3;
                    size_t dst = ((size_t)(h * 32 + blk) * 16 + j0s + kcl) * 4096
                               + (size_t)((((n & 7) * 2 + dhi) * 4 + krhi) * 64 + off);
                    *(float4*)&g_vT[dst] = *(const float4*)&Ap[b * 64 + off];
                }
            }
            __syncthreads();
        }
    } else {
        int idx = blockIdx.x - 1024;
        int i = idx & 511, h = idx >> 9;
        if (t < DK) qv[t] = g_q[i * 128 + h * DK + t];
        if (t < 3)  cai[t] = Ca[i * 3 + t];
        __syncthreads();

        float bin = (float)(4 * (h + 1)) / 10.0f;
        float bin2 = bin * bin;
        const float scaling = 0.17677669529663687f;
        float cx = cai[0], cy = cai[1], cz = cai[2];

        float sc[2];
        #pragma unroll
        for (int u = 0; u < 2; u++) {
            int j = t + u * 256;
            float dx = Ca[3 * j] - cx, dy = Ca[3 * j + 1] - cy, dz = Ca[3 * j + 2] - cz;
            float sq = fmaxf(dx * dx + dy * dy + dz * dz, 1e-12f);
            if (sq > bin2) {
                sc[u] = NEGMAX;
            } else {
                float a = 0.0f;
                const float* kp = &g_k[j * 128 + h * DK];
                #pragma unroll
                for (int d = 0; d < DK; d++) a += qv[d] * kp[d];
                sc[u] = a * scaling;
            }
        }
        float mx = fmaxf(sc[0], sc[1]);
        #pragma unroll
        for (int o = 16; o; o >>= 1) mx = fmaxf(mx, __shfl_xor_sync(0xffffffffu, mx, o));
        if ((t & 31) == 0) red[t >> 5] = mx;
        __syncthreads();
        mx = red[0];
        #pragma unroll
        for (int w = 1; w < 8; w++) mx = fmaxf(mx, red[w]);

        float e0 = expf(sc[0] - mx);
        float e1 = expf(sc[1] - mx);
        float ss = e0 + e1;
        #pragma unroll
        for (int o = 16; o; o >>= 1) ss += __shfl_xor_sync(0xffffffffu, ss, o);
        __syncthreads();
        if ((t & 31) == 0) red[t >> 5] = ss;
        __syncthreads();
        ss = red[0];
        #pragma unroll
        for (int w = 1; w < 8; w++) ss += red[w];
        float inv = 1.0f / ss;

        int iblk = i >> 7, ib = i & 127;
        size_t blkbase = ((size_t)(h * 4 + iblk) * 16) * 4096;
        float vals[2] = {e0 * inv, e1 * inv};
        #pragma unroll
        for (int u = 0; u < 2; u++) {
            int j = t + u * 256;
            int kc = j >> 5;
            g_attn[blkbase + (size_t)kc * 4096 + afrag_addr(ib, j & 31, 4)] = vals[u];
        }
    }
}

// =====================================================================
// K3 (mma tf32 + cp.async 3-stage): per-head C = attn @ vT.  grid=(32,4,4)
// =====================================================================
extern __shared__ float gsh[];
__global__ void __launch_bounds__(256, 2) gemm_attn_mma() {
    int h  = blockIdx.z;
    const float* __restrict__ Abase =
        g_attn + ((size_t)(h * 4 + blockIdx.y) * 16) * 4096;
    const float* __restrict__ Bbase =
        g_vT + ((size_t)(h * 32 + blockIdx.x) * 16) * 4096;

    float* sA = gsh;
    float* sB = gsh + 12288;

    int t = threadIdx.x, wid = t >> 5, lid = t & 31;
    int wm = wid >> 2, wn = wid & 3;
    uint32_t aAddr = smem_u32(sA) + t * 16;
    uint32_t bAddr = smem_u32(sB) + t * 16;

    float acc[4][4][4];
    #pragma unroll
    for (int x = 0; x < 4; x++)
        #pragma unroll
        for (int y = 0; y < 4; y++)
            #pragma unroll
            for (int r = 0; r < 4; r++) acc[x][y][r] = 0.0f;

    #pragma unroll 1
    for (int p = 0; p < 2; p++) {
        const float4* srcA = (const float4*)(Abase + (size_t)p * 4096) + t;
        const float4* srcB = (const float4*)(Bbase + (size_t)p * 4096) + t;
        #pragma unroll
        for (int u = 0; u < 4; u++) {
            cp16(aAddr + p * 16384 + u * 4096, srcA + u * 256);
            cp16(bAddr + p * 16384 + u * 4096, srcB + u * 256);
        }
        CP_COMMIT();
    }

    #pragma unroll 1
    for (int kc = 0; kc < 16; kc++) {
        if (kc + 2 < 16) {
            int st = (kc + 2) % 3;
            const float4* srcA = (const float4*)(Abase + (size_t)(kc + 2) * 4096) + t;
            const float4* srcB = (const float4*)(Bbase + (size_t)(kc + 2) * 4096) + t;
            #pragma unroll
            for (int u = 0; u < 4; u++) {
                cp16(aAddr + st * 16384 + u * 4096, srcA + u * 256);
                cp16(bAddr + st * 16384 + u * 4096, srcB + u * 256);
            }
        }
        CP_COMMIT();
        CP_WAIT2();
        __syncthreads();
        const float* cA = sA + (kc % 3) * 4096;
        const float* cB = sB + (kc % 3) * 4096;
        #pragma unroll
        for (int ks = 0; ks < 4; ks++) {
            uint32_t bf[4][2];
            #pragma unroll
            for (int nt2 = 0; nt2 < 4; nt2++) {
                int nt = wn * 4 + nt2;
                float2 b2 = *(const float2*)&cB[(nt * 4 + ks) * 64 + lid * 2];
                bf[nt2][0] = F2U(b2.x);
                bf[nt2][1] = F2U(b2.y);
            }
            #pragma unroll
            for (int mt2 = 0; mt2 < 4; mt2++) {
                int mt = wm * 4 + mt2;
                float4 a4 = *(const float4*)&cA[(mt * 4 + ks) * 128 + lid * 4];
                #pragma unroll
                for (int nt2 = 0; nt2 < 4; nt2++)
                    mma_tf32(acc[mt2][nt2][0], acc[mt2][nt2][1],
                             acc[mt2][nt2][2], acc[mt2][nt2][3],
                             F2U(a4.x), F2U(a4.y), F2U(a4.z), F2U(a4.w),
                             bf[nt2][0], bf[nt2][1]);
            }
        }
        __syncthreads();
    }

    float* stg = gsh;
    int rg = lid >> 2, q2 = (lid & 3) * 2;
    #pragma unroll
    for (int mt2 = 0; mt2 < 4; mt2++) {
        #pragma unroll
        for (int nt2 = 0; nt2 < 4; nt2++) {
            int nloc = wn * 2 + (nt2 >> 1);
            #pragma unroll
            for (int e = 0; e < 4; e++) {
                int rt = mt2 * 16 + rg + (e >> 1) * 8;
                int d = (nt2 & 1) * 8 + q2 + (e & 1);
                int sidx = (((wm * 8 + nloc) * 2 + (d >> 3)) * 4 + mt2) * 128
                         + (rt & 7) * 16 + ((rt >> 3) & 1)
                         + (d & 3) * 4 + ((d >> 2) & 1) * 2;
                stg[sidx] = acc[mt2][nt2][e];
            }
        }
    }
    __syncthreads();
    #pragma unroll
    for (int u = 0; u < 16; u++) {
        int f = t + u * 256;
        int b = f >> 5;
        int off = (f & 31) * 4;
        int krt = b & 3, dhi = (b >> 2) & 1, nloc = (b >> 3) & 7, iloc = b >> 6;
        int n = blockIdx.x * 8 + nloc;
        size_t rtile = (size_t)n * 8 + blockIdx.y * 2 + iloc;
        size_t dst = rtile * 4096 + (size_t)((krt * 8 + h * 2 + dhi) * 128 + off);
        *(float4*)&g_attout[dst] = *(const float4*)&stg[b * 128 + off];
    }
}

// =====================================================================
// K5 (mma tf32): msax = msa + attout@Wo + bo.  grid=683, ~3 tiles/CTA,
// double-buffered cp.async Ap load.  dyn smem: Wop[4096] + Ap[2][4096].
// =====================================================================
__global__ void __launch_bounds__(256) oproj_mma_kernel(
        const float* __restrict__ msa,
        const float* __restrict__ Wo, const float* __restrict__ bo) {
    float* Wop = gsh;                 // [4096]
    float* Apb = gsh + 4096;          // [2][4096]
    __shared__ float sbo[DM];
    int t = threadIdx.x, warp = t >> 5, lane = t & 31;
    int rg = lane >> 2, q2 = (lane & 3) * 2;
    int wm = warp >> 2, wn = warp & 3;
    uint32_t apAddr = smem_u32(Apb) + t * 16;

    // prologue: async-load first tile while permuting weights
    {
        const float4* src = (const float4*)(g_attout + (size_t)blockIdx.x * 4096) + t;
        #pragma unroll
        for (int u = 0; u < 4; u++)
            cp16(apAddr + u * 4096, src + u * 256);
        CP_COMMIT();
    }
    for (int i = t; i < 4096; i += 256) {
        int c = i >> 6, n = i & 63;
        Wop[bfrag_addr(c, n, 8)] = Wo[i];
    }
    if (t < DM) sbo[t] = bo[t];

    int buf = 0;
    for (int tile = blockIdx.x; tile < NROWS / 64; tile += gridDim.x) {
        int nxt = tile + gridDim.x;
        if (nxt < NROWS / 64) {
            const float4* src = (const float4*)(g_attout + (size_t)nxt * 4096) + t;
            #pragma unroll
            for (int u = 0; u < 4; u++)
                cp16(apAddr + (buf ^ 1) * 16384 + u * 4096, src + u * 256);
        }
        CP_COMMIT();
        CP_WAIT1();
        __syncthreads();
        const float* cAp = Apb + buf * 4096;
        size_t row0 = (size_t)tile * 64;

        float acc[2][2][4];
        #pragma unroll
        for (int x = 0; x < 2; x++)
            #pragma unroll
            for (int y = 0; y < 2; y++)
                #pragma unroll
                for (int r = 0; r < 4; r++) acc[x][y][r] = 0.0f;
        #pragma unroll
        for (int ks = 0; ks < 8; ks++) {
            float4 af[2];
            float2 bf[2];
            #pragma unroll
            for (int mt = 0; mt < 2; mt++)
                af[mt] = *(const float4*)&cAp[((wm * 2 + mt) * 8 + ks) * 128 + lane * 4];
            #pragma unroll
            for (int nt = 0; nt < 2; nt++)
                bf[nt] = *(const float2*)&Wop[((wn * 2 + nt) * 8 + ks) * 64 + lane * 2];
            #pragma unroll
            for (int mt = 0; mt < 2; mt++)
                #pragma unroll
                for (int nt = 0; nt < 2; nt++)
                    mma_tf32(acc[mt][nt][0], acc[mt][nt][1], acc[mt][nt][2], acc[mt][nt][3],
                             F2U(af[mt].x), F2U(af[mt].y), F2U(af[mt].z), F2U(af[mt].w),
                             F2U(bf[nt].x), F2U(bf[nt].y));
        }
        #pragma unroll
        for (int mt = 0; mt < 2; mt++) {
            #pragma unroll
            for (int nt = 0; nt < 2; nt++) {
                int rt0 = wm * 32 + mt * 16 + rg;
                int c0 = wn * 16 + nt * 8 + q2;
                float bo0 = sbo[c0], bo1 = sbo[c0 + 1];
                #pragma unroll
                for (int half = 0; half < 2; half++) {
                    size_t r = row0 + rt0 + half * 8;
                    float2 m2 = *(const float2*)&msa[r * DM + c0];
                    *(float2*)&g_msax[r * DM + c0] =
                        make_float2(acc[mt][nt][half * 2]     + bo0 + m2.x,
                                    acc[mt][nt][half * 2 + 1] + bo1 + m2.y);
                }
            }
        }
        __syncthreads();     // all reads of Ap[buf] done before it is refilled
        buf ^= 1;
    }
}

// =====================================================================
// K6 (mma tf32, 512 threads): fused FF + final LN.
// 16 warps: GEMM1 2m x 8n; GEMM2 2m x 2n x 4k-split (partials in Ps).
// Combine phase folded into LN3 (register-sum of 4 partials + residual).
// =====================================================================
struct FFS4 {
    float W1p[DM * FFH];
    float W2p[FFH * DM];
    float b1s[FFH];
    float b2s[DM], g2[DM], bn2[DM], g3[DM], bn3[DM];
    float Xs[64 * DM];
    float Ap[64 * DM];
    float Hp[64 * FFH];
};
extern __shared__ unsigned char ff_raw[];

__global__ void __launch_bounds__(512) ff_mma_kernel(
        const float* __restrict__ n2g, const float* __restrict__ n2b,
        const float* __restrict__ W1, const float* __restrict__ b1,
        const float* __restrict__ W2, const float* __restrict__ b2,
        const float* __restrict__ n3g, const float* __restrict__ n3b,
        float* __restrict__ out) {
    FFS4* s = (FFS4*)ff_raw;
    int t = threadIdx.x, warp = t >> 5, lane = t & 31;
    int rg = lane >> 2, q2 = (lane & 3) * 2;

    for (int i = t; i < DM * FFH; i += 512) {
        int c = i >> 8, n = i & 255;
        s->W1p[bfrag_addr(c, n, 8)] = W1[i];
    }
    for (int i = t; i < FFH * DM; i += 512) {
        int c = i >> 6, n = i & 63;
        s->W2p[bfrag_addr(c, n, 32)] = W2[i];
    }
    if (t < FFH) s->b1s[t] = b1[t];
    if (t < DM) { s->b2s[t] = b2[t]; s->g2[t] = n2g[t]; s->bn2[t] = n2b[t];
                  s->g3[t] = n3g[t]; s->bn3[t] = n3b[t]; }
    __syncthreads();

    const int nTiles = NROWS / 64;
    float4 xr[2];
    if (blockIdx.x < nTiles) {
        const float4* src = (const float4*)&g_msax[(size_t)blockIdx.x * 4096];
        #pragma unroll
        for (int i = 0; i < 2; i++) xr[i] = src[t * 2 + i];
    }

    for (int tile = blockIdx.x; tile < nTiles; tile += gridDim.x) {
        size_t row0 = (size_t)tile * 64;
        #pragma unroll
        for (int i = 0; i < 2; i++)
            *(float4*)&s->Xs[(t * 2 + i) * 4] = xr[i];
        __syncthreads();
        int nxt = tile + gridDim.x;
        if (nxt < nTiles) {
            const float4* src = (const float4*)&g_msax[(size_t)nxt * 4096];
            #pragma unroll
            for (int i = 0; i < 2; i++) xr[i] = src[t * 2 + i];
        }
        #pragma unroll
        for (int rr = 0; rr < 4; rr++) {
            int row = warp * 4 + rr;
            float2 x2 = *(const float2*)&s->Xs[row * DM + 2 * lane];
            float sum = x2.x + x2.y;
            #pragma unroll
            for (int o = 16; o; o >>= 1) sum += __shfl_xor_sync(0xffffffffu, sum, o);
            float m = sum * (1.0f / DM);
            float d0 = x2.x - m, d1 = x2.y - m;
            float vv = d0 * d0 + d1 * d1;
            #pragma unroll
            for (int o = 16; o; o >>= 1) vv += __shfl_xor_sync(0xffffffffu, vv, o);
            float r = rsqrtf(vv * (1.0f / DM) + EPSLN);
            int c0 = 2 * lane;
            s->Ap[afrag_addr(row, c0, 8)]     = d0 * r * s->g2[c0]     + s->bn2[c0];
            s->Ap[afrag_addr(row, c0 + 1, 8)] = d1 * r * s->g2[c0 + 1] + s->bn2[c0 + 1];
        }
        __syncthreads();
        {
            int wm = warp >> 3, wn = warp & 7;
            float acc1[2][4][4];
            #pragma unroll
            for (int x = 0; x < 2; x++)
                #pragma unroll
                for (int y = 0; y < 4; y++)
                    #pragma unroll
                    for (int r = 0; r < 4; r++) acc1[x][y][r] = 0.0f;
            #pragma unroll
            for (int ks = 0; ks < 8; ks++) {
                float4 af0 = *(const float4*)&s->Ap[((wm * 2 + 0) * 8 + ks) * 128 + lane * 4];
                float4 af1 = *(const float4*)&s->Ap[((wm * 2 + 1) * 8 + ks) * 128 + lane * 4];
                #pragma unroll
                for (int nt = 0; nt < 4; nt++) {
                    float2 b2v = *(const float2*)&s->W1p[((wn * 4 + nt) * 8 + ks) * 64 + lane * 2];
                    mma_tf32(acc1[0][nt][0], acc1[0][nt][1], acc1[0][nt][2], acc1[0][nt][3],
                             F2U(af0.x), F2U(af0.y), F2U(af0.z), F2U(af0.w),
                             F2U(b2v.x), F2U(b2v.y));
                    mma_tf32(acc1[1][nt][0], acc1[1][nt][1], acc1[1][nt][2], acc1[1][nt][3],
                             F2U(af1.x), F2U(af1.y), F2U(af1.z), F2U(af1.w),
                             F2U(b2v.x), F2U(b2v.y));
                }
            }
            #pragma unroll
            for (int mt = 0; mt < 2; mt++) {
                int mtg = wm * 2 + mt;
                #pragma unroll
                for (int nt = 0; nt < 4; nt++) {
                    int ks2 = wn * 4 + nt;
                    int c0 = ks2 * 8 + q2;
                    float b1a = s->b1s[c0], b1b = s->b1s[c0 + 1];
                    float v0 = fmaxf(acc1[mt][nt][0] + b1a, 0.f);
                    float v1 = fmaxf(acc1[mt][nt][1] + b1b, 0.f);
                    float v2 = fmaxf(acc1[mt][nt][2] + b1a, 0.f);
                    float v3 = fmaxf(acc1[mt][nt][3] + b1b, 0.f);
                    int fb = (mtg * 32 + ks2) * 128 + rg * 16;
                    int a0 = fb + (q2 & 3) * 4 + ((q2 >> 2) << 1);
                    int kk1 = q2 + 1;
                    int a1 = fb + (kk1 & 3) * 4 + ((kk1 >> 2) << 1);
                    *(float2*)&s->Hp[a0] = make_float2(v0, v2);
                    *(float2*)&s->Hp[a1] = make_float2(v1, v3);
                }
            }
        }
        __syncthreads();
        {
            int kg = warp >> 2;
            int wm2 = (warp >> 1) & 1, wn2 = warp & 1;
            float acc2[2][4][4];
            #pragma unroll
            for (int x = 0; x < 2; x++)
                #pragma unroll
                for (int y = 0; y < 4; y++)
                    #pragma unroll
                    for (int r = 0; r < 4; r++) acc2[x][y][r] = 0.0f;
            #pragma unroll
            for (int ks = 0; ks < 8; ks++) {
                int ksg = kg * 8 + ks;
                float4 af0 = *(const float4*)&s->Hp[((wm2 * 2 + 0) * 32 + ksg) * 128 + lane * 4];
                float4 af1 = *(const float4*)&s->Hp[((wm2 * 2 + 1) * 32 + ksg) * 128 + lane * 4];
                #pragma unroll
                for (int nt = 0; nt < 4; nt++) {
                    float2 b2v = *(const float2*)&s->W2p[((wn2 * 4 + nt) * 32 + ksg) * 64 + lane * 2];
                    mma_tf32(acc2[0][nt][0], acc2[0][nt][1], acc2[0][nt][2], acc2[0][nt][3],
                             F2U(af0.x), F2U(af0.y), F2U(af0.z), F2U(af0.w),
                             F2U(b2v.x), F2U(b2v.y));
                    mma_tf32(acc2[1][nt][0], acc2[1][nt][1], acc2[1][nt][2], acc2[1][nt][3],
                             F2U(af1.x), F2U(af1.y), F2U(af1.z), F2U(af1.w),
                             F2U(b2v.x), F2U(b2v.y));
                }
            }
            __syncthreads();
            float* Ps = s->Ap;
            #pragma unroll
            for (int mt = 0; mt < 2; mt++)
                #pragma unroll
                for (int nt = 0; nt < 4; nt++) {
                    int r0 = wm2 * 32 + mt * 16 + rg;
                    int c0 = wn2 * 32 + nt * 8 + q2;
                    *(float2*)&Ps[kg * 4608 + r0 * 72 + c0] =
                        make_float2(acc2[mt][nt][0], acc2[mt][nt][1]);
                    *(float2*)&Ps[kg * 4608 + (r0 + 8) * 72 + c0] =
                        make_float2(acc2[mt][nt][2], acc2[mt][nt][3]);
                }
        }
        __syncthreads();
        // ---- fused combine + LN3: 4 rows/warp -> out ----
        {
            float* Ps = s->Ap;
            #pragma unroll
            for (int rr = 0; rr < 4; rr++) {
                int row = warp * 4 + rr;
                int c0 = 2 * lane;
                float2 x2 = *(const float2*)&s->Xs[row * DM + c0];
                float2 p0 = *(const float2*)&Ps[row * 72 + c0];
                float2 p1 = *(const float2*)&Ps[4608 + row * 72 + c0];
                float2 p2 = *(const float2*)&Ps[9216 + row * 72 + c0];
                float2 p3 = *(const float2*)&Ps[13824 + row * 72 + c0];
                float y0 = x2.x + s->b2s[c0]     + p0.x + p1.x + p2.x + p3.x;
                float y1 = x2.y + s->b2s[c0 + 1] + p0.y + p1.y + p2.y + p3.y;
                float sum = y0 + y1;
                #pragma unroll
                for (int o = 16; o; o >>= 1) sum += __shfl_xor_sync(0xffffffffu, sum, o);
                float m = sum * (1.0f / DM);
                float d0 = y0 - m, d1 = y1 - m;
                float vv = d0 * d0 + d1 * d1;
                #pragma unroll
                for (int o = 16; o; o >>= 1) vv += __shfl_xor_sync(0xffffffffu, vv, o);
                float r = rsqrtf(vv * (1.0f / DM) + EPSLN);
                size_t ob = (row0 + row) * DM;
                out[ob + c0]     = d0 * r * s->g3[c0]     + s->bn3[c0];
                out[ob + c0 + 1] = d1 * r * s->g3[c0 + 1] + s->bn3[c0 + 1];
            }
        }
        __syncthreads();
    }
}

// =====================================================================
extern "C" void kernel_launch(void* const* d_in, const int* in_sizes, int n_in,
                              void* d_out, int out_size) {
    const float* msa   = (const float*)d_in[0];
    const float* Ca    = (const float*)d_in[1];
    const float* state = (const float*)d_in[2];
    const float* ns_g  = (const float*)d_in[3];
    const float* ns_b  = (const float*)d_in[4];
    const float* n1_g  = (const float*)d_in[5];
    const float* n1_b  = (const float*)d_in[6];
    const float* Wq    = (const float*)d_in[7];
    const float* bq    = (const float*)d_in[8];
    const float* Wk    = (const float*)d_in[9];
    const float* bk    = (const float*)d_in[10];
    const float* Wv    = (const float*)d_in[11];
    const float* bv    = (const float*)d_in[12];
    const float* Wo    = (const float*)d_in[13];
    const float* bo    = (const float*)d_in[14];
    const float* n2_g  = (const float*)d_in[15];
    const float* n2_b  = (const float*)d_in[16];
    const float* W1    = (const float*)d_in[17];
    const float* b1    = (const float*)d_in[18];
    const float* W2    = (const float*)d_in[19];
    const float* b2    = (const float*)d_in[20];
    const float* n3_g  = (const float*)d_in[21];
    const float* n3_b  = (const float*)d_in[22];
    float* out = (float*)d_out;

    cudaFuncSetAttribute(ff_mma_kernel, cudaFuncAttributeMaxDynamicSharedMemorySize,
                         (int)sizeof(FFS4));
    cudaFuncSetAttribute(gemm_attn_mma, cudaFuncAttributeMaxDynamicSharedMemorySize,
                         98304);
    cudaFuncSetAttribute(oproj_mma_kernel, cudaFuncAttributeMaxDynamicSharedMemorySize,
                         49152);

    qk_kernel<<<L, 128>>>(state, ns_g, ns_b, Wq, bq, Wk, bk);
    prep_kernel<<<3072, 256>>>(Ca, msa, n1_g, n1_b, Wv, bv);
    gemm_attn_mma<<<dim3(32, 4, 4), 256, 98304>>>();
    oproj_mma_kernel<<<683, 256, 49152>>>(msa, Wo, bo);
    ff_mma_kernel<<<148, 512, sizeof(FFS4)>>>(n2_g, n2_b, W1, b1, W2, b2, n3_g, n3_b, out);
}

// round 16
// speedup vs baseline: 1.0719x; 1.0083x over previous
#include <cuda_runtime.h>
#include <cuda_bf16.h>
#include <math.h>
#include <stdint.h>

// ---------------- problem constants ----------------
#define L 512
#define NSEQ 256
#define DM 64
#define DS 32
#define NH 4
#define DK 32
#define DV 16
#define FFH 256
#define NROWS (NSEQ * L)
#define EPSLN 1e-5f
#define NEGMAX (-3.402823466e38f)

// ---------------- scratch ----------------
__device__ float g_q[L * NH * DK];
__device__ float g_k[L * NH * DK];
__device__ float g_attn[NH * L * L];          // A-frag: [h][iblk(4)][kc(16)][4096]
__device__ float g_vT[NH * L * NSEQ * DV];    // B-frag: [h][nblk(32)][kc(16)][4096]
__device__ float g_attout[NROWS * DM];        // A-frag 64-row tiles: [tile][4096]
__device__ float g_msax[NROWS * DM];          // raw rows

__device__ __forceinline__ void mma_tf32(float& c0, float& c1, float& c2, float& c3,
                                         uint32_t a0, uint32_t a1, uint32_t a2, uint32_t a3,
                                         uint32_t b0, uint32_t b1) {
    asm volatile(
        "mma.sync.aligned.m16n8k8.row.col.f32.tf32.tf32.f32 "
        "{%0,%1,%2,%3}, {%4,%5,%6,%7}, {%8,%9}, {%0,%1,%2,%3};"
        : "+f"(c0), "+f"(c1), "+f"(c2), "+f"(c3)
        : "r"(a0), "r"(a1), "r"(a2), "r"(a3), "r"(b0), "r"(b1));
}
#define F2U(x) __float_as_uint(x)

__device__ __forceinline__ uint32_t smem_u32(const void* p) {
    uint32_t a;
    asm("{ .reg .u64 tmp; cvta.to.shared.u64 tmp, %1; cvt.u32.u64 %0, tmp; }"
        : "=r"(a) : "l"(p));
    return a;
}
__device__ __forceinline__ void cp16(uint32_t smem, const void* gmem) {
    asm volatile("cp.async.cg.shared.global [%0], [%1], 16;" :: "r"(smem), "l"(gmem));
}
#define CP_COMMIT() asm volatile("cp.async.commit_group;")
#define CP_WAIT2()  asm volatile("cp.async.wait_group 2;")
#define CP_WAIT1()  asm volatile("cp.async.wait_group 1;")

__device__ __forceinline__ int afrag_addr(int r, int c, int KS8) {
    return ((r >> 4) * KS8 + (c >> 3)) * 128 + (r & 7) * 16 + ((r >> 3) & 1)
         + (c & 3) * 4 + ((c >> 2) & 1) * 2;
}
__device__ __forceinline__ int bfrag_addr(int c, int n, int KS8) {
    return ((n >> 3) * KS8 + (c >> 3)) * 64 + (n & 7) * 8 + (c & 3) * 2 + ((c >> 2) & 1);
}

// =====================================================================
// K1: st = LN(state); q,k projections.  grid=512, block=128
// =====================================================================
__global__ void qk_kernel(const float* __restrict__ state,
                          const float* __restrict__ nsg, const float* __restrict__ nsb,
                          const float* __restrict__ Wq, const float* __restrict__ bq,
                          const float* __restrict__ Wk, const float* __restrict__ bk) {
    int l = blockIdx.x;
    int t = threadIdx.x;
    __shared__ float st[DS];
    if (t < DS) {
        float x = state[l * DS + t];
        float s = x;
        #pragma unroll
        for (int o = 16; o; o >>= 1) s += __shfl_xor_sync(0xffffffffu, s, o);
        float m = s * (1.0f / DS);
        float d = x - m;
        float v = d * d;
        #pragma unroll
        for (int o = 16; o; o >>= 1) v += __shfl_xor_sync(0xffffffffu, v, o);
        float r = rsqrtf(v * (1.0f / DS) + EPSLN);
        st[t] = d * r * nsg[t] + nsb[t];
    }
    __syncthreads();
    float aq = bq[t], ak = bk[t];
    #pragma unroll
    for (int c = 0; c < DS; c++) {
        float s = st[c];
        aq += s * Wq[c * 128 + t];
        ak += s * Wk[c * 128 + t];
    }
    g_q[l * 128 + t] = aq;
    g_k[l * 128 + t] = ak;
}

// =====================================================================
// K2 (fused): blocks [0,1024) = v path; blocks [1024,3072) = attn softmax.
// =====================================================================
__global__ void __launch_bounds__(256) prep_kernel(
        const float* __restrict__ Ca,
        const float* __restrict__ msa,
        const float* __restrict__ n1g, const float* __restrict__ n1b,
        const float* __restrict__ Wv, const float* __restrict__ bv) {
    __shared__ float Wvp[4096];
    __shared__ float Ap[4096];
    __shared__ float sbv[DM], sg[DM], sb[DM];
    __shared__ float qv[DK];
    __shared__ float red[8];
    __shared__ float cai[3];

    int t = threadIdx.x;

    if (blockIdx.x < 1024) {
        int warp = t >> 5, lane = t & 31;
        int rg = lane >> 2, q2 = (lane & 3) * 2;
        for (int i = t; i < 4096; i += 256) {
            int c = i >> 6, n = i & 63;
            Wvp[bfrag_addr(c, n, 8)] = Wv[i];
        }
        if (t < DM) { sbv[t] = bv[t]; sg[t] = n1g[t]; sb[t] = n1b[t]; }
        __syncthreads();

        int wm = warp >> 2, wn = warp & 3;
        for (int tile = blockIdx.x; tile < NROWS / 64; tile += 1024) {
            size_t row0 = (size_t)tile * 64;
            #pragma unroll
            for (int rr = 0; rr < 8; rr++) {
                int row = warp * 8 + rr;
                float2 x2 = *(const float2*)&msa[(row0 + row) * DM + 2 * lane];
                float sum = x2.x + x2.y;
                #pragma unroll
                for (int o = 16; o; o >>= 1) sum += __shfl_xor_sync(0xffffffffu, sum, o);
                float m = sum * (1.0f / DM);
                float d0 = x2.x - m, d1 = x2.y - m;
                float vv = d0 * d0 + d1 * d1;
                #pragma unroll
                for (int o = 16; o; o >>= 1) vv += __shfl_xor_sync(0xffffffffu, vv, o);
                float r = rsqrtf(vv * (1.0f / DM) + EPSLN);
                int c0 = 2 * lane;
                Ap[afrag_addr(row, c0, 8)]     = d0 * r * sg[c0]     + sb[c0];
                Ap[afrag_addr(row, c0 + 1, 8)] = d1 * r * sg[c0 + 1] + sb[c0 + 1];
            }
            __syncthreads();
            float acc[2][2][4];
            #pragma unroll
            for (int x = 0; x < 2; x++)
                #pragma unroll
                for (int y = 0; y < 2; y++)
                    #pragma unroll
                    for (int r = 0; r < 4; r++) acc[x][y][r] = 0.0f;
            #pragma unroll
            for (int ks = 0; ks < 8; ks++) {
                float4 af[2];
                float2 bf[2];
                #pragma unroll
                for (int mt = 0; mt < 2; mt++)
                    af[mt] = *(const float4*)&Ap[((wm * 2 + mt) * 8 + ks) * 128 + lane * 4];
                #pragma unroll
                for (int nt = 0; nt < 2; nt++)
                    bf[nt] = *(const float2*)&Wvp[((wn * 2 + nt) * 8 + ks) * 64 + lane * 2];
                #pragma unroll
                for (int mt = 0; mt < 2; mt++)
                    #pragma unroll
                    for (int nt = 0; nt < 2; nt++)
                        mma_tf32(acc[mt][nt][0], acc[mt][nt][1], acc[mt][nt][2], acc[mt][nt][3],
                                 F2U(af[mt].x), F2U(af[mt].y), F2U(af[mt].z), F2U(af[mt].w),
                                 F2U(bf[nt].x), F2U(bf[nt].y));
            }
            __syncthreads();
            #pragma unroll
            for (int mt = 0; mt < 2; mt++) {
                #pragma unroll
                for (int nt = 0; nt < 2; nt++) {
                    int rt0 = wm * 32 + mt * 16 + rg;
                    int c0 = wn * 16 + nt * 8 + q2;
                    #pragma unroll
                    for (int e = 0; e < 4; e++) {
                        int rt = rt0 + (e >> 1) * 8;
                        int cc = c0 + (e & 1);
                        int h = cc >> 4, d = cc & 15;
                        int sidx = ((((h * 2 + (rt >> 5)) * 2 + (d >> 3)) * 4)
                                    + ((rt >> 3) & 3)) * 64
                                 + (d & 7) * 8 + (rt & 3) * 2 + ((rt >> 2) & 1);
                        Ap[sidx] = acc[mt][nt][e] + sbv[cc];
                    }
                }
            }
            __syncthreads();
            {
                int n = (int)(row0 >> 9);
                int j0s = (int)((row0 & 511) >> 5);
                int blk = n >> 3;
                #pragma unroll
                for (int u = 0; u < 4; u++) {
                    int f = t + u * 256;
                    int b = f >> 4;
                    int off = (f & 15) * 4;
                    int h = b >> 4, kcl = (b >> 3) & 1, dhi = (b >> 2) & 1, krhi = b & 3;
                    size_t dst = ((size_t)(h * 32 + blk) * 16 + j0s + kcl) * 4096
                               + (size_t)((((n & 7) * 2 + dhi) * 4 + krhi) * 64 + off);
                    *(float4*)&g_vT[dst] = *(const float4*)&Ap[b * 64 + off];
                }
            }
            __syncthreads();
        }
    } else {
        int idx = blockIdx.x - 1024;
        int i = idx & 511, h = idx >> 9;
        if (t < DK) qv[t] = g_q[i * 128 + h * DK + t];
        if (t < 3)  cai[t] = Ca[i * 3 + t];
        __syncthreads();

        float bin = (float)(4 * (h + 1)) / 10.0f;
        float bin2 = bin * bin;
        const float scaling = 0.17677669529663687f;
        float cx = cai[0], cy = cai[1], cz = cai[2];

        float sc[2];
        #pragma unroll
        for (int u = 0; u < 2; u++) {
            int j = t + u * 256;
            float dx = Ca[3 * j] - cx, dy = Ca[3 * j + 1] - cy, dz = Ca[3 * j + 2] - cz;
            float sq = fmaxf(dx * dx + dy * dy + dz * dz, 1e-12f);
            if (sq > bin2) {
                sc[u] = NEGMAX;
            } else {
                float a = 0.0f;
                const float* kp = &g_k[j * 128 + h * DK];
                #pragma unroll
                for (int d = 0; d < DK; d++) a += qv[d] * kp[d];
                sc[u] = a * scaling;
            }
        }
        float mx = fmaxf(sc[0], sc[1]);
        #pragma unroll
        for (int o = 16; o; o >>= 1) mx = fmaxf(mx, __shfl_xor_sync(0xffffffffu, mx, o));
        if ((t & 31) == 0) red[t >> 5] = mx;
        __syncthreads();
        mx = red[0];
        #pragma unroll
        for (int w = 1; w < 8; w++) mx = fmaxf(mx, red[w]);

        float e0 = expf(sc[0] - mx);
        float e1 = expf(sc[1] - mx);
        float ss = e0 + e1;
        #pragma unroll
        for (int o = 16; o; o >>= 1) ss += __shfl_xor_sync(0xffffffffu, ss, o);
        __syncthreads();
        if ((t & 31) == 0) red[t >> 5] = ss;
        __syncthreads();
        ss = red[0];
        #pragma unroll
        for (int w = 1; w < 8; w++) ss += red[w];
        float inv = 1.0f / ss;

        int iblk = i >> 7, ib = i & 127;
        size_t blkbase = ((size_t)(h * 4 + iblk) * 16) * 4096;
        float vals[2] = {e0 * inv, e1 * inv};
        #pragma unroll
        for (int u = 0; u < 2; u++) {
            int j = t + u * 256;
            int kc = j >> 5;
            g_attn[blkbase + (size_t)kc * 4096 + afrag_addr(ib, j & 31, 4)] = vals[u];
        }
    }
}

// =====================================================================
// K3 (mma tf32 + cp.async 3-stage): per-head C = attn @ vT.  grid=(32,4,4)
// =====================================================================
extern __shared__ float gsh[];
__global__ void __launch_bounds__(256, 2) gemm_attn_mma() {
    int h  = blockIdx.z;
    const float* __restrict__ Abase =
        g_attn + ((size_t)(h * 4 + blockIdx.y) * 16) * 4096;
    const float* __restrict__ Bbase =
        g_vT + ((size_t)(h * 32 + blockIdx.x) * 16) * 4096;

    float* sA = gsh;
    float* sB = gsh + 12288;

    int t = threadIdx.x, wid = t >> 5, lid = t & 31;
    int wm = wid >> 2, wn = wid & 3;
    uint32_t aAddr = smem_u32(sA) + t * 16;
    uint32_t bAddr = smem_u32(sB) + t * 16;

    float acc[4][4][4];
    #pragma unroll
    for (int x = 0; x < 4; x++)
        #pragma unroll
        for (int y = 0; y < 4; y++)
            #pragma unroll
            for (int r = 0; r < 4; r++) acc[x][y][r] = 0.0f;

    #pragma unroll 1
    for (int p = 0; p < 2; p++) {
        const float4* srcA = (const float4*)(Abase + (size_t)p * 4096) + t;
        const float4* srcB = (const float4*)(Bbase + (size_t)p * 4096) + t;
        #pragma unroll
        for (int u = 0; u < 4; u++) {
            cp16(aAddr + p * 16384 + u * 4096, srcA + u * 256);
            cp16(bAddr + p * 16384 + u * 4096, srcB + u * 256);
        }
        CP_COMMIT();
    }

    #pragma unroll 1
    for (int kc = 0; kc < 16; kc++) {
        if (kc + 2 < 16) {
            int st = (kc + 2) % 3;
            const float4* srcA = (const float4*)(Abase + (size_t)(kc + 2) * 4096) + t;
            const float4* srcB = (const float4*)(Bbase + (size_t)(kc + 2) * 4096) + t;
            #pragma unroll
            for (int u = 0; u < 4; u++) {
                cp16(aAddr + st * 16384 + u * 4096, srcA + u * 256);
                cp16(bAddr + st * 16384 + u * 4096, srcB + u * 256);
            }
        }
        CP_COMMIT();
        CP_WAIT2();
        __syncthreads();
        const float* cA = sA + (kc % 3) * 4096;
        const float* cB = sB + (kc % 3) * 4096;
        #pragma unroll
        for (int ks = 0; ks < 4; ks++) {
            uint32_t bf[4][2];
            #pragma unroll
            for (int nt2 = 0; nt2 < 4; nt2++) {
                int nt = wn * 4 + nt2;
                float2 b2 = *(const float2*)&cB[(nt * 4 + ks) * 64 + lid * 2];
                bf[nt2][0] = F2U(b2.x);
                bf[nt2][1] = F2U(b2.y);
            }
            #pragma unroll
            for (int mt2 = 0; mt2 < 4; mt2++) {
                int mt = wm * 4 + mt2;
                float4 a4 = *(const float4*)&cA[(mt * 4 + ks) * 128 + lid * 4];
                #pragma unroll
                for (int nt2 = 0; nt2 < 4; nt2++)
                    mma_tf32(acc[mt2][nt2][0], acc[mt2][nt2][1],
                             acc[mt2][nt2][2], acc[mt2][nt2][3],
                             F2U(a4.x), F2U(a4.y), F2U(a4.z), F2U(a4.w),
                             bf[nt2][0], bf[nt2][1]);
            }
        }
        __syncthreads();
    }

    float* stg = gsh;
    int rg = lid >> 2, q2 = (lid & 3) * 2;
    #pragma unroll
    for (int mt2 = 0; mt2 < 4; mt2++) {
        #pragma unroll
        for (int nt2 = 0; nt2 < 4; nt2++) {
            int nloc = wn * 2 + (nt2 >> 1);
            #pragma unroll
            for (int e = 0; e < 4; e++) {
                int rt = mt2 * 16 + rg + (e >> 1) * 8;
                int d = (nt2 & 1) * 8 + q2 + (e & 1);
                int sidx = (((wm * 8 + nloc) * 2 + (d >> 3)) * 4 + mt2) * 128
                         + (rt & 7) * 16 + ((rt >> 3) & 1)
                         + (d & 3) * 4 + ((d >> 2) & 1) * 2;
                stg[sidx] = acc[mt2][nt2][e];
            }
        }
    }
    __syncthreads();
    #pragma unroll
    for (int u = 0; u < 16; u++) {
        int f = t + u * 256;
        int b = f >> 5;
        int off = (f & 31) * 4;
        int krt = b & 3, dhi = (b >> 2) & 1, nloc = (b >> 3) & 7, iloc = b >> 6;
        int n = blockIdx.x * 8 + nloc;
        size_t rtile = (size_t)n * 8 + blockIdx.y * 2 + iloc;
        size_t dst = rtile * 4096 + (size_t)((krt * 8 + h * 2 + dhi) * 128 + off);
        *(float4*)&g_attout[dst] = *(const float4*)&stg[b * 128 + off];
    }
}

// =====================================================================
// K5 (mma tf32): msax = msa + attout@Wo + bo.  grid=1024, 2 tiles/CTA,
// double-buffered cp.async Ap load.  dyn smem: Wop[4096] + Ap[2][4096].
// =====================================================================
__global__ void __launch_bounds__(256) oproj_mma_kernel(
        const float* __restrict__ msa,
        const float* __restrict__ Wo, const float* __restrict__ bo) {
    float* Wop = gsh;                 // [4096]
    float* Apb = gsh + 4096;          // [2][4096]
    __shared__ float sbo[DM];
    int t = threadIdx.x, warp = t >> 5, lane = t & 31;
    int rg = lane >> 2, q2 = (lane & 3) * 2;
    int wm = warp >> 2, wn = warp & 3;
    uint32_t apAddr = smem_u32(Apb) + t * 16;

    // prologue: async-load first tile while permuting weights
    {
        const float4* src = (const float4*)(g_attout + (size_t)blockIdx.x * 4096) + t;
        #pragma unroll
        for (int u = 0; u < 4; u++)
            cp16(apAddr + u * 4096, src + u * 256);
        CP_COMMIT();
    }
    for (int i = t; i < 4096; i += 256) {
        int c = i >> 6, n = i & 63;
        Wop[bfrag_addr(c, n, 8)] = Wo[i];
    }
    if (t < DM) sbo[t] = bo[t];

    int buf = 0;
    for (int tile = blockIdx.x; tile < NROWS / 64; tile += gridDim.x) {
        int nxt = tile + gridDim.x;
        if (nxt < NROWS / 64) {
            const float4* src = (const float4*)(g_attout + (size_t)nxt * 4096) + t;
            #pragma unroll
            for (int u = 0; u < 4; u++)
                cp16(apAddr + (buf ^ 1) * 16384 + u * 4096, src + u * 256);
        }
        CP_COMMIT();
        CP_WAIT1();
        __syncthreads();
        const float* cAp = Apb + buf * 4096;
        size_t row0 = (size_t)tile * 64;

        float acc[2][2][4];
        #pragma unroll
        for (int x = 0; x < 2; x++)
            #pragma unroll
            for (int y = 0; y < 2; y++)
                #pragma unroll
                for (int r = 0; r < 4; r++) acc[x][y][r] = 0.0f;
        #pragma unroll
        for (int ks = 0; ks < 8; ks++) {
            float4 af[2];
            float2 bf[2];
            #pragma unroll
            for (int mt = 0; mt < 2; mt++)
                af[mt] = *(const float4*)&cAp[((wm * 2 + mt) * 8 + ks) * 128 + lane * 4];
            #pragma unroll
            for (int nt = 0; nt < 2; nt++)
                bf[nt] = *(const float2*)&Wop[((wn * 2 + nt) * 8 + ks) * 64 + lane * 2];
            #pragma unroll
            for (int mt = 0; mt < 2; mt++)
                #pragma unroll
                for (int nt = 0; nt < 2; nt++)
                    mma_tf32(acc[mt][nt][0], acc[mt][nt][1], acc[mt][nt][2], acc[mt][nt][3],
                             F2U(af[mt].x), F2U(af[mt].y), F2U(af[mt].z), F2U(af[mt].w),
                             F2U(bf[nt].x), F2U(bf[nt].y));
        }
        #pragma unroll
        for (int mt = 0; mt < 2; mt++) {
            #pragma unroll
            for (int nt = 0; nt < 2; nt++) {
                int rt0 = wm * 32 + mt * 16 + rg;
                int c0 = wn * 16 + nt * 8 + q2;
                float bo0 = sbo[c0], bo1 = sbo[c0 + 1];
                #pragma unroll
                for (int half = 0; half < 2; half++) {
                    size_t r = row0 + rt0 + half * 8;
                    float2 m2 = *(const float2*)&msa[r * DM + c0];
                    *(float2*)&g_msax[r * DM + c0] =
                        make_float2(acc[mt][nt][half * 2]     + bo0 + m2.x,
                                    acc[mt][nt][half * 2 + 1] + bo1 + m2.y);
                }
            }
        }
        __syncthreads();     // all reads of Ap[buf] done before it is refilled
        buf ^= 1;
    }
}

// =====================================================================
// K6 (mma tf32, 512 threads): fused FF + final LN.
// 16 warps: GEMM1 2m x 8n; GEMM2 2m x 2n x 4k-split (partials in Ps).
// Combine phase folded into LN3 (register-sum of 4 partials + residual).
// =====================================================================
struct FFS4 {
    float W1p[DM * FFH];
    float W2p[FFH * DM];
    float b1s[FFH];
    float b2s[DM], g2[DM], bn2[DM], g3[DM], bn3[DM];
    float Xs[64 * DM];
    float Ap[64 * DM];
    float Hp[64 * FFH];
};
extern __shared__ unsigned char ff_raw[];

__global__ void __launch_bounds__(512) ff_mma_kernel(
        const float* __restrict__ n2g, const float* __restrict__ n2b,
        const float* __restrict__ W1, const float* __restrict__ b1,
        const float* __restrict__ W2, const float* __restrict__ b2,
        const float* __restrict__ n3g, const float* __restrict__ n3b,
        float* __restrict__ out) {
    FFS4* s = (FFS4*)ff_raw;
    int t = threadIdx.x, warp = t >> 5, lane = t & 31;
    int rg = lane >> 2, q2 = (lane & 3) * 2;

    for (int i = t; i < DM * FFH; i += 512) {
        int c = i >> 8, n = i & 255;
        s->W1p[bfrag_addr(c, n, 8)] = W1[i];
    }
    for (int i = t; i < FFH * DM; i += 512) {
        int c = i >> 6, n = i & 63;
        s->W2p[bfrag_addr(c, n, 32)] = W2[i];
    }
    if (t < FFH) s->b1s[t] = b1[t];
    if (t < DM) { s->b2s[t] = b2[t]; s->g2[t] = n2g[t]; s->bn2[t] = n2b[t];
                  s->g3[t] = n3g[t]; s->bn3[t] = n3b[t]; }
    __syncthreads();

    const int nTiles = NROWS / 64;
    float4 xr[2];
    if (blockIdx.x < nTiles) {
        const float4* src = (const float4*)&g_msax[(size_t)blockIdx.x * 4096];
        #pragma unroll
        for (int i = 0; i < 2; i++) xr[i] = src[t * 2 + i];
    }

    for (int tile = blockIdx.x; tile < nTiles; tile += gridDim.x) {
        size_t row0 = (size_t)tile * 64;
        #pragma unroll
        for (int i = 0; i < 2; i++)
            *(float4*)&s->Xs[(t * 2 + i) * 4] = xr[i];
        __syncthreads();
        int nxt = tile + gridDim.x;
        if (nxt < nTiles) {
            const float4* src = (const float4*)&g_msax[(size_t)nxt * 4096];
            #pragma unroll
            for (int i = 0; i < 2; i++) xr[i] = src[t * 2 + i];
        }
        #pragma unroll
        for (int rr = 0; rr < 4; rr++) {
            int row = warp * 4 + rr;
            float2 x2 = *(const float2*)&s->Xs[row * DM + 2 * lane];
            float sum = x2.x + x2.y;
            #pragma unroll
            for (int o = 16; o; o >>= 1) sum += __shfl_xor_sync(0xffffffffu, sum, o);
            float m = sum * (1.0f / DM);
            float d0 = x2.x - m, d1 = x2.y - m;
            float vv = d0 * d0 + d1 * d1;
            #pragma unroll
            for (int o = 16; o; o >>= 1) vv += __shfl_xor_sync(0xffffffffu, vv, o);
            float r = rsqrtf(vv * (1.0f / DM) + EPSLN);
            int c0 = 2 * lane;
            s->Ap[afrag_addr(row, c0, 8)]     = d0 * r * s->g2[c0]     + s->bn2[c0];
            s->Ap[afrag_addr(row, c0 + 1, 8)] = d1 * r * s->g2[c0 + 1] + s->bn2[c0 + 1];
        }
        __syncthreads();
        {
            int wm = warp >> 3, wn = warp & 7;
            float acc1[2][4][4];
            #pragma unroll
            for (int x = 0; x < 2; x++)
                #pragma unroll
                for (int y = 0; y < 4; y++)
                    #pragma unroll
                    for (int r = 0; r < 4; r++) acc1[x][y][r] = 0.0f;
            #pragma unroll
            for (int ks = 0; ks < 8; ks++) {
                float4 af0 = *(const float4*)&s->Ap[((wm * 2 + 0) * 8 + ks) * 128 + lane * 4];
                float4 af1 = *(const float4*)&s->Ap[((wm * 2 + 1) * 8 + ks) * 128 + lane * 4];
                #pragma unroll
                for (int nt = 0; nt < 4; nt++) {
                    float2 b2v = *(const float2*)&s->W1p[((wn * 4 + nt) * 8 + ks) * 64 + lane * 2];
                    mma_tf32(acc1[0][nt][0], acc1[0][nt][1], acc1[0][nt][2], acc1[0][nt][3],
                             F2U(af0.x), F2U(af0.y), F2U(af0.z), F2U(af0.w),
                             F2U(b2v.x), F2U(b2v.y));
                    mma_tf32(acc1[1][nt][0], acc1[1][nt][1], acc1[1][nt][2], acc1[1][nt][3],
                             F2U(af1.x), F2U(af1.y), F2U(af1.z), F2U(af1.w),
                             F2U(b2v.x), F2U(b2v.y));
                }
            }
            #pragma unroll
            for (int mt = 0; mt < 2; mt++) {
                int mtg = wm * 2 + mt;
                #pragma unroll
                for (int nt = 0; nt < 4; nt++) {
                    int ks2 = wn * 4 + nt;
                    int c0 = ks2 * 8 + q2;
                    float b1a = s->b1s[c0], b1b = s->b1s[c0 + 1];
                    float v0 = fmaxf(acc1[mt][nt][0] + b1a, 0.f);
                    float v1 = fmaxf(acc1[mt][nt][1] + b1b, 0.f);
                    float v2 = fmaxf(acc1[mt][nt][2] + b1a, 0.f);
                    float v3 = fmaxf(acc1[mt][nt][3] + b1b, 0.f);
                    int fb = (mtg * 32 + ks2) * 128 + rg * 16;
                    int a0 = fb + (q2 & 3) * 4 + ((q2 >> 2) << 1);
                    int kk1 = q2 + 1;
                    int a1 = fb + (kk1 & 3) * 4 + ((kk1 >> 2) << 1);
                    *(float2*)&s->Hp[a0] = make_float2(v0, v2);
                    *(float2*)&s->Hp[a1] = make_float2(v1, v3);
                }
            }
        }
        __syncthreads();
        {
            int kg = warp >> 2;
            int wm2 = (warp >> 1) & 1, wn2 = warp & 1;
            float acc2[2][4][4];
            #pragma unroll
            for (int x = 0; x < 2; x++)
                #pragma unroll
                for (int y = 0; y < 4; y++)
                    #pragma unroll
                    for (int r = 0; r < 4; r++) acc2[x][y][r] = 0.0f;
            #pragma unroll
            for (int ks = 0; ks < 8; ks++) {
                int ksg = kg * 8 + ks;
                float4 af0 = *(const float4*)&s->Hp[((wm2 * 2 + 0) * 32 + ksg) * 128 + lane * 4];
                float4 af1 = *(const float4*)&s->Hp[((wm2 * 2 + 1) * 32 + ksg) * 128 + lane * 4];
                #pragma unroll
                for (int nt = 0; nt < 4; nt++) {
                    float2 b2v = *(const float2*)&s->W2p[((wn2 * 4 + nt) * 32 + ksg) * 64 + lane * 2];
                    mma_tf32(acc2[0][nt][0], acc2[0][nt][1], acc2[0][nt][2], acc2[0][nt][3],
                             F2U(af0.x), F2U(af0.y), F2U(af0.z), F2U(af0.w),
                             F2U(b2v.x), F2U(b2v.y));
                    mma_tf32(acc2[1][nt][0], acc2[1][nt][1], acc2[1][nt][2], acc2[1][nt][3],
                             F2U(af1.x), F2U(af1.y), F2U(af1.z), F2U(af1.w),
                             F2U(b2v.x), F2U(b2v.y));
                }
            }
            __syncthreads();
            float* Ps = s->Ap;
            #pragma unroll
            for (int mt = 0; mt < 2; mt++)
                #pragma unroll
                for (int nt = 0; nt < 4; nt++) {
                    int r0 = wm2 * 32 + mt * 16 + rg;
                    int c0 = wn2 * 32 + nt * 8 + q2;
                    *(float2*)&Ps[kg * 4608 + r0 * 72 + c0] =
                        make_float2(acc2[mt][nt][0], acc2[mt][nt][1]);
                    *(float2*)&Ps[kg * 4608 + (r0 + 8) * 72 + c0] =
                        make_float2(acc2[mt][nt][2], acc2[mt][nt][3]);
                }
        }
        __syncthreads();
        // ---- fused combine + LN3: 4 rows/warp -> out ----
        {
            float* Ps = s->Ap;
            #pragma unroll
            for (int rr = 0; rr < 4; rr++) {
                int row = warp * 4 + rr;
                int c0 = 2 * lane;
                float2 x2 = *(const float2*)&s->Xs[row * DM + c0];
                float2 p0 = *(const float2*)&Ps[row * 72 + c0];
                float2 p1 = *(const float2*)&Ps[4608 + row * 72 + c0];
                float2 p2 = *(const float2*)&Ps[9216 + row * 72 + c0];
                float2 p3 = *(const float2*)&Ps[13824 + row * 72 + c0];
                float y0 = x2.x + s->b2s[c0]     + p0.x + p1.x + p2.x + p3.x;
                float y1 = x2.y + s->b2s[c0 + 1] + p0.y + p1.y + p2.y + p3.y;
                float sum = y0 + y1;
                #pragma unroll
                for (int o = 16; o; o >>= 1) sum += __shfl_xor_sync(0xffffffffu, sum, o);
                float m = sum * (1.0f / DM);
                float d0 = y0 - m, d1 = y1 - m;
                float vv = d0 * d0 + d1 * d1;
                #pragma unroll
                for (int o = 16; o; o >>= 1) vv += __shfl_xor_sync(0xffffffffu, vv, o);
                float r = rsqrtf(vv * (1.0f / DM) + EPSLN);
                size_t ob = (row0 + row) * DM;
                out[ob + c0]     = d0 * r * s->g3[c0]     + s->bn3[c0];
                out[ob + c0 + 1] = d1 * r * s->g3[c0 + 1] + s->bn3[c0 + 1];
            }
        }
        __syncthreads();
    }
}

// =====================================================================
extern "C" void kernel_launch(void* const* d_in, const int* in_sizes, int n_in,
                              void* d_out, int out_size) {
    const float* msa   = (const float*)d_in[0];
    const float* Ca    = (const float*)d_in[1];
    const float* state = (const float*)d_in[2];
    const float* ns_g  = (const float*)d_in[3];
    const float* ns_b  = (const float*)d_in[4];
    const float* n1_g  = (const float*)d_in[5];
    const float* n1_b  = (const float*)d_in[6];
    const float* Wq    = (const float*)d_in[7];
    const float* bq    = (const float*)d_in[8];
    const float* Wk    = (const float*)d_in[9];
    const float* bk    = (const float*)d_in[10];
    const float* Wv    = (const float*)d_in[11];
    const float* bv    = (const float*)d_in[12];
    const float* Wo    = (const float*)d_in[13];
    const float* bo    = (const float*)d_in[14];
    const float* n2_g  = (const float*)d_in[15];
    const float* n2_b  = (const float*)d_in[16];
    const float* W1    = (const float*)d_in[17];
    const float* b1    = (const float*)d_in[18];
    const float* W2    = (const float*)d_in[19];
    const float* b2    = (const float*)d_in[20];
    const float* n3_g  = (const float*)d_in[21];
    const float* n3_b  = (const float*)d_in[22];
    float* out = (float*)d_out;

    cudaFuncSetAttribute(ff_mma_kernel, cudaFuncAttributeMaxDynamicSharedMemorySize,
                         (int)sizeof(FFS4));
    cudaFuncSetAttribute(gemm_attn_mma, cudaFuncAttributeMaxDynamicSharedMemorySize,
                         98304);
    cudaFuncSetAttribute(oproj_mma_kernel, cudaFuncAttributeMaxDynamicSharedMemorySize,
                         49152);

    qk_kernel<<<L, 128>>>(state, ns_g, ns_b, Wq, bq, Wk, bk);
    prep_kernel<<<3072, 256>>>(Ca, msa, n1_g, n1_b, Wv, bv);
    gemm_attn_mma<<<dim3(32, 4, 4), 256, 98304>>>();
    oproj_mma_kernel<<<1024, 256, 49152>>>(msa, Wo, bo);
    ff_mma_kernel<<<148, 512, sizeof(FFS4)>>>(n2_g, n2_b, W1, b1, W2, b2, n3_g, n3_b, out);
}

// round 17
// speedup vs baseline: 1.1012x; 1.0274x over previous
#include <cuda_runtime.h>
#include <cuda_bf16.h>
#include <math.h>
#include <stdint.h>

// ---------------- problem constants ----------------
#define L 512
#define NSEQ 256
#define DM 64
#define DS 32
#define NH 4
#define DK 32
#define DV 16
#define FFH 256
#define NROWS (NSEQ * L)
#define EPSLN 1e-5f
#define NEGMAX (-3.402823466e38f)

// ---------------- scratch ----------------
__device__ float g_q[L * NH * DK];
__device__ float g_k[L * NH * DK];
__device__ float g_attn[NH * L * L];          // A-frag: [h][iblk(4)][kc(16)][4096]
__device__ float g_vT[NH * L * NSEQ * DV];    // B-frag: [h][nblk(32)][kc(16)][4096]
__device__ float g_attout[NROWS * DM];        // A-frag 64-row tiles: [tile][4096]
__device__ float g_msax[NROWS * DM];          // raw rows

__device__ __forceinline__ void mma_tf32(float& c0, float& c1, float& c2, float& c3,
                                         uint32_t a0, uint32_t a1, uint32_t a2, uint32_t a3,
                                         uint32_t b0, uint32_t b1) {
    asm volatile(
        "mma.sync.aligned.m16n8k8.row.col.f32.tf32.tf32.f32 "
        "{%0,%1,%2,%3}, {%4,%5,%6,%7}, {%8,%9}, {%0,%1,%2,%3};"
        : "+f"(c0), "+f"(c1), "+f"(c2), "+f"(c3)
        : "r"(a0), "r"(a1), "r"(a2), "r"(a3), "r"(b0), "r"(b1));
}
#define F2U(x) __float_as_uint(x)

__device__ __forceinline__ uint32_t smem_u32(const void* p) {
    uint32_t a;
    asm("{ .reg .u64 tmp; cvta.to.shared.u64 tmp, %1; cvt.u32.u64 %0, tmp; }"
        : "=r"(a) : "l"(p));
    return a;
}
__device__ __forceinline__ void cp16(uint32_t smem, const void* gmem) {
    asm volatile("cp.async.cg.shared.global [%0], [%1], 16;" :: "r"(smem), "l"(gmem));
}
#define CP_COMMIT() asm volatile("cp.async.commit_group;")
#define CP_WAIT2()  asm volatile("cp.async.wait_group 2;")
#define CP_WAIT1()  asm volatile("cp.async.wait_group 1;")

__device__ __forceinline__ int afrag_addr(int r, int c, int KS8) {
    return ((r >> 4) * KS8 + (c >> 3)) * 128 + (r & 7) * 16 + ((r >> 3) & 1)
         + (c & 3) * 4 + ((c >> 2) & 1) * 2;
}
__device__ __forceinline__ int bfrag_addr(int c, int n, int KS8) {
    return ((n >> 3) * KS8 + (c >> 3)) * 64 + (n & 7) * 8 + (c & 3) * 2 + ((c >> 2) & 1);
}

extern __shared__ float gsh[];

// =====================================================================
// K1: st = LN(state); q,k projections.  grid=512, block=128
// =====================================================================
__global__ void qk_kernel(const float* __restrict__ state,
                          const float* __restrict__ nsg, const float* __restrict__ nsb,
                          const float* __restrict__ Wq, const float* __restrict__ bq,
                          const float* __restrict__ Wk, const float* __restrict__ bk) {
    int l = blockIdx.x;
    int t = threadIdx.x;
    __shared__ float st[DS];
    if (t < DS) {
        float x = state[l * DS + t];
        float s = x;
        #pragma unroll
        for (int o = 16; o; o >>= 1) s += __shfl_xor_sync(0xffffffffu, s, o);
        float m = s * (1.0f / DS);
        float d = x - m;
        float v = d * d;
        #pragma unroll
        for (int o = 16; o; o >>= 1) v += __shfl_xor_sync(0xffffffffu, v, o);
        float r = rsqrtf(v * (1.0f / DS) + EPSLN);
        st[t] = d * r * nsg[t] + nsb[t];
    }
    __syncthreads();
    float aq = bq[t], ak = bk[t];
    #pragma unroll
    for (int c = 0; c < DS; c++) {
        float s = st[c];
        aq += s * Wq[c * 128 + t];
        ak += s * Wk[c * 128 + t];
    }
    g_q[l * 128 + t] = aq;
    g_k[l * 128 + t] = ak;
}

// =====================================================================
// K2 (fused, dyn smem): blocks [0,1024) = v path;
// blocks [1024,1152) = attn softmax, 16 rows/block, staged + coalesced.
// =====================================================================
__global__ void __launch_bounds__(256) prep_kernel(
        const float* __restrict__ Ca,
        const float* __restrict__ msa,
        const float* __restrict__ n1g, const float* __restrict__ n1b,
        const float* __restrict__ Wv, const float* __restrict__ bv) {
    __shared__ float sbv[DM], sg[DM], sb[DM];

    int t = threadIdx.x;
    int warp = t >> 5, lane = t & 31;

    if (blockIdx.x < 1024) {
        // ================= v path =================
        float* Wvp = gsh;            // [4096]
        float* Ap  = gsh + 4096;     // [4096]
        int rg = lane >> 2, q2 = (lane & 3) * 2;
        for (int i = t; i < 4096; i += 256) {
            int c = i >> 6, n = i & 63;
            Wvp[bfrag_addr(c, n, 8)] = Wv[i];
        }
        if (t < DM) { sbv[t] = bv[t]; sg[t] = n1g[t]; sb[t] = n1b[t]; }
        __syncthreads();

        int wm = warp >> 2, wn = warp & 3;
        for (int tile = blockIdx.x; tile < NROWS / 64; tile += 1024) {
            size_t row0 = (size_t)tile * 64;
            #pragma unroll
            for (int rr = 0; rr < 8; rr++) {
                int row = warp * 8 + rr;
                float2 x2 = *(const float2*)&msa[(row0 + row) * DM + 2 * lane];
                float sum = x2.x + x2.y;
                #pragma unroll
                for (int o = 16; o; o >>= 1) sum += __shfl_xor_sync(0xffffffffu, sum, o);
                float m = sum * (1.0f / DM);
                float d0 = x2.x - m, d1 = x2.y - m;
                float vv = d0 * d0 + d1 * d1;
                #pragma unroll
                for (int o = 16; o; o >>= 1) vv += __shfl_xor_sync(0xffffffffu, vv, o);
                float r = rsqrtf(vv * (1.0f / DM) + EPSLN);
                int c0 = 2 * lane;
                Ap[afrag_addr(row, c0, 8)]     = d0 * r * sg[c0]     + sb[c0];
                Ap[afrag_addr(row, c0 + 1, 8)] = d1 * r * sg[c0 + 1] + sb[c0 + 1];
            }
            __syncthreads();
            float acc[2][2][4];
            #pragma unroll
            for (int x = 0; x < 2; x++)
                #pragma unroll
                for (int y = 0; y < 2; y++)
                    #pragma unroll
                    for (int r = 0; r < 4; r++) acc[x][y][r] = 0.0f;
            #pragma unroll
            for (int ks = 0; ks < 8; ks++) {
                float4 af[2];
                float2 bf[2];
                #pragma unroll
                for (int mt = 0; mt < 2; mt++)
                    af[mt] = *(const float4*)&Ap[((wm * 2 + mt) * 8 + ks) * 128 + lane * 4];
                #pragma unroll
                for (int nt = 0; nt < 2; nt++)
                    bf[nt] = *(const float2*)&Wvp[((wn * 2 + nt) * 8 + ks) * 64 + lane * 2];
                #pragma unroll
                for (int mt = 0; mt < 2; mt++)
                    #pragma unroll
                    for (int nt = 0; nt < 2; nt++)
                        mma_tf32(acc[mt][nt][0], acc[mt][nt][1], acc[mt][nt][2], acc[mt][nt][3],
                                 F2U(af[mt].x), F2U(af[mt].y), F2U(af[mt].z), F2U(af[mt].w),
                                 F2U(bf[nt].x), F2U(bf[nt].y));
            }
            __syncthreads();
            #pragma unroll
            for (int mt = 0; mt < 2; mt++) {
                #pragma unroll
                for (int nt = 0; nt < 2; nt++) {
                    int rt0 = wm * 32 + mt * 16 + rg;
                    int c0 = wn * 16 + nt * 8 + q2;
                    #pragma unroll
                    for (int e = 0; e < 4; e++) {
                        int rt = rt0 + (e >> 1) * 8;
                        int cc = c0 + (e & 1);
                        int h = cc >> 4, d = cc & 15;
                        int sidx = ((((h * 2 + (rt >> 5)) * 2 + (d >> 3)) * 4)
                                    + ((rt >> 3) & 3)) * 64
                                 + (d & 7) * 8 + (rt & 3) * 2 + ((rt >> 2) & 1);
                        Ap[sidx] = acc[mt][nt][e] + sbv[cc];
                    }
                }
            }
            __syncthreads();
            {
                int n = (int)(row0 >> 9);
                int j0s = (int)((row0 & 511) >> 5);
                int blk = n >> 3;
                #pragma unroll
                for (int u = 0; u < 4; u++) {
                    int f = t + u * 256;
                    int b = f >> 4;
                    int off = (f & 15) * 4;
                    int h = b >> 4, kcl = (b >> 3) & 1, dhi = (b >> 2) & 1, krhi = b & 3;
                    size_t dst = ((size_t)(h * 32 + blk) * 16 + j0s + kcl) * 4096
                               + (size_t)((((n & 7) * 2 + dhi) * 4 + krhi) * 64 + off);
                    *(float4*)&g_vT[dst] = *(const float4*)&Ap[b * 64 + off];
                }
            }
            __syncthreads();
        }
    } else {
        // ================= attn path: 16 rows per block =================
        float* Es   = gsh;            // [16][516]  (8256)
        float* Ks   = gsh + 8256;     // [128][33]  (4224)
        float* Qs   = gsh + 12480;    // [16][32]   (512)
        float* Caj  = gsh + 12992;    // [128*3]    (384)
        float* caiS = gsh + 13376;    // [48]
        float* sInv = gsh + 13424;    // [16]

        int idx = blockIdx.x - 1024;
        int h = idx >> 5, ig = idx & 31;
        int i0 = ig * 16;

        float bin = (float)(4 * (h + 1)) / 10.0f;
        float bin2 = bin * bin;
        const float scaling = 0.17677669529663687f;

        for (int id = t; id < 512; id += 256)
            Qs[id] = g_q[(size_t)(i0 + (id >> 5)) * 128 + h * DK + (id & 31)];
        for (int id = t; id < 48; id += 256)
            caiS[id] = Ca[(size_t)i0 * 3 + id];
        __syncthreads();

        #pragma unroll 1
        for (int jc = 0; jc < 4; jc++) {
            for (int id = t; id < 1024; id += 256) {
                int j = id >> 3, d4 = (id & 7) * 4;
                float4 kv = *(const float4*)&g_k[(size_t)(jc * 128 + j) * 128 + h * DK + d4];
                Ks[j * 33 + d4]     = kv.x;
                Ks[j * 33 + d4 + 1] = kv.y;
                Ks[j * 33 + d4 + 2] = kv.z;
                Ks[j * 33 + d4 + 3] = kv.w;
            }
            for (int id = t; id < 384; id += 256)
                Caj[id] = Ca[(size_t)(jc * 128) * 3 + id];
            __syncthreads();
            #pragma unroll
            for (int rr2 = 0; rr2 < 2; rr2++) {
                int rloc = warp * 2 + rr2;
                float cx = caiS[rloc * 3], cy = caiS[rloc * 3 + 1], cz = caiS[rloc * 3 + 2];
                #pragma unroll
                for (int it = 0; it < 4; it++) {
                    int j = it * 32 + lane;
                    float dx = Caj[j * 3] - cx, dy = Caj[j * 3 + 1] - cy, dz = Caj[j * 3 + 2] - cz;
                    float sq = fmaxf(dx * dx + dy * dy + dz * dz, 1e-12f);
                    float sc;
                    if (sq > bin2) {
                        sc = NEGMAX;
                    } else {
                        float a = 0.0f;
                        #pragma unroll
                        for (int d = 0; d < DK; d++)
                            a += Qs[rloc * 32 + d] * Ks[j * 33 + d];
                        sc = a * scaling;
                    }
                    Es[rloc * 516 + jc * 128 + j] = sc;
                }
            }
            __syncthreads();
        }
        // softmax per row (2 rows per warp)
        #pragma unroll
        for (int rr2 = 0; rr2 < 2; rr2++) {
            int rloc = warp * 2 + rr2;
            float mx = NEGMAX;
            #pragma unroll
            for (int it = 0; it < 16; it++)
                mx = fmaxf(mx, Es[rloc * 516 + it * 32 + lane]);
            #pragma unroll
            for (int o = 16; o; o >>= 1) mx = fmaxf(mx, __shfl_xor_sync(0xffffffffu, mx, o));
            float s = 0.0f;
            #pragma unroll
            for (int it = 0; it < 16; it++) {
                float e = expf(Es[rloc * 516 + it * 32 + lane] - mx);
                Es[rloc * 516 + it * 32 + lane] = e;
                s += e;
            }
            #pragma unroll
            for (int o = 16; o; o >>= 1) s += __shfl_xor_sync(0xffffffffu, s, o);
            if (lane == 0) sInv[rloc] = 1.0f / s;
        }
        __syncthreads();
        // coalesced write: 64 complete afrag blocks
        int iblk = i0 >> 7, mt = (i0 & 127) >> 4;
        size_t blkbase = ((size_t)(h * 4 + iblk) * 16) * 4096;
        #pragma unroll
        for (int u = 0; u < 8; u++) {
            int f = t + u * 256;
            int b = f >> 5, q = f & 31;
            int kc = b >> 2, ks = b & 3;
            int rl = (q >> 2) & 7, kkl = q & 3;
            int jb = kc * 32 + ks * 8 + kkl;
            float i0v = sInv[rl], i1v = sInv[rl + 8];
            float4 v = make_float4(Es[rl * 516 + jb] * i0v,
                                   Es[(rl + 8) * 516 + jb] * i1v,
                                   Es[rl * 516 + jb + 4] * i0v,
                                   Es[(rl + 8) * 516 + jb + 4] * i1v);
            *(float4*)&g_attn[blkbase + (size_t)kc * 4096 + (mt * 4 + ks) * 128 + q * 4] = v;
        }
    }
}

// =====================================================================
// K3 (mma tf32 + cp.async 3-stage): per-head C = attn @ vT.  grid=(32,4,4)
// =====================================================================
__global__ void __launch_bounds__(256, 2) gemm_attn_mma() {
    int h  = blockIdx.z;
    const float* __restrict__ Abase =
        g_attn + ((size_t)(h * 4 + blockIdx.y) * 16) * 4096;
    const float* __restrict__ Bbase =
        g_vT + ((size_t)(h * 32 + blockIdx.x) * 16) * 4096;

    float* sA = gsh;
    float* sB = gsh + 12288;

    int t = threadIdx.x, wid = t >> 5, lid = t & 31;
    int wm = wid >> 2, wn = wid & 3;
    uint32_t aAddr = smem_u32(sA) + t * 16;
    uint32_t bAddr = smem_u32(sB) + t * 16;

    float acc[4][4][4];
    #pragma unroll
    for (int x = 0; x < 4; x++)
        #pragma unroll
        for (int y = 0; y < 4; y++)
            #pragma unroll
            for (int r = 0; r < 4; r++) acc[x][y][r] = 0.0f;

    #pragma unroll 1
    for (int p = 0; p < 2; p++) {
        const float4* srcA = (const float4*)(Abase + (size_t)p * 4096) + t;
        const float4* srcB = (const float4*)(Bbase + (size_t)p * 4096) + t;
        #pragma unroll
        for (int u = 0; u < 4; u++) {
            cp16(aAddr + p * 16384 + u * 4096, srcA + u * 256);
            cp16(bAddr + p * 16384 + u * 4096, srcB + u * 256);
        }
        CP_COMMIT();
    }

    #pragma unroll 1
    for (int kc = 0; kc < 16; kc++) {
        if (kc + 2 < 16) {
            int st = (kc + 2) % 3;
            const float4* srcA = (const float4*)(Abase + (size_t)(kc + 2) * 4096) + t;
            const float4* srcB = (const float4*)(Bbase + (size_t)(kc + 2) * 4096) + t;
            #pragma unroll
            for (int u = 0; u < 4; u++) {
                cp16(aAddr + st * 16384 + u * 4096, srcA + u * 256);
                cp16(bAddr + st * 16384 + u * 4096, srcB + u * 256);
            }
        }
        CP_COMMIT();
        CP_WAIT2();
        __syncthreads();
        const float* cA = sA + (kc % 3) * 4096;
        const float* cB = sB + (kc % 3) * 4096;
        #pragma unroll
        for (int ks = 0; ks < 4; ks++) {
            uint32_t bf[4][2];
            #pragma unroll
            for (int nt2 = 0; nt2 < 4; nt2++) {
                int nt = wn * 4 + nt2;
                float2 b2 = *(const float2*)&cB[(nt * 4 + ks) * 64 + lid * 2];
                bf[nt2][0] = F2U(b2.x);
                bf[nt2][1] = F2U(b2.y);
            }
            #pragma unroll
            for (int mt2 = 0; mt2 < 4; mt2++) {
                int mt = wm * 4 + mt2;
                float4 a4 = *(const float4*)&cA[(mt * 4 + ks) * 128 + lid * 4];
                #pragma unroll
                for (int nt2 = 0; nt2 < 4; nt2++)
                    mma_tf32(acc[mt2][nt2][0], acc[mt2][nt2][1],
                             acc[mt2][nt2][2], acc[mt2][nt2][3],
                             F2U(a4.x), F2U(a4.y), F2U(a4.z), F2U(a4.w),
                             bf[nt2][0], bf[nt2][1]);
            }
        }
        __syncthreads();
    }

    float* stg = gsh;
    int rg = lid >> 2, q2 = (lid & 3) * 2;
    #pragma unroll
    for (int mt2 = 0; mt2 < 4; mt2++) {
        #pragma unroll
        for (int nt2 = 0; nt2 < 4; nt2++) {
            int nloc = wn * 2 + (nt2 >> 1);
            #pragma unroll
            for (int e = 0; e < 4; e++) {
                int rt = mt2 * 16 + rg + (e >> 1) * 8;
                int d = (nt2 & 1) * 8 + q2 + (e & 1);
                int sidx = (((wm * 8 + nloc) * 2 + (d >> 3)) * 4 + mt2) * 128
                         + (rt & 7) * 16 + ((rt >> 3) & 1)
                         + (d & 3) * 4 + ((d >> 2) & 1) * 2;
                stg[sidx] = acc[mt2][nt2][e];
            }
        }
    }
    __syncthreads();
    #pragma unroll
    for (int u = 0; u < 16; u++) {
        int f = t + u * 256;
        int b = f >> 5;
        int off = (f & 31) * 4;
        int krt = b & 3, dhi = (b >> 2) & 1, nloc = (b >> 3) & 7, iloc = b >> 6;
        int n = blockIdx.x * 8 + nloc;
        size_t rtile = (size_t)n * 8 + blockIdx.y * 2 + iloc;
        size_t dst = rtile * 4096 + (size_t)((krt * 8 + h * 2 + dhi) * 128 + off);
        *(float4*)&g_attout[dst] = *(const float4*)&stg[b * 128 + off];
    }
}

// =====================================================================
// K5 (mma tf32): msax = msa + attout@Wo + bo.  grid=1024, 2 tiles/CTA,
// double-buffered cp.async Ap load.  dyn smem: Wop[4096] + Ap[2][4096].
// =====================================================================
__global__ void __launch_bounds__(256) oproj_mma_kernel(
        const float* __restrict__ msa,
        const float* __restrict__ Wo, const float* __restrict__ bo) {
    float* Wop = gsh;                 // [4096]
    float* Apb = gsh + 4096;          // [2][4096]
    __shared__ float sbo[DM];
    int t = threadIdx.x, warp = t >> 5, lane = t & 31;
    int rg = lane >> 2, q2 = (lane & 3) * 2;
    int wm = warp >> 2, wn = warp & 3;
    uint32_t apAddr = smem_u32(Apb) + t * 16;

    {
        const float4* src = (const float4*)(g_attout + (size_t)blockIdx.x * 4096) + t;
        #pragma unroll
        for (int u = 0; u < 4; u++)
            cp16(apAddr + u * 4096, src + u * 256);
        CP_COMMIT();
    }
    for (int i = t; i < 4096; i += 256) {
        int c = i >> 6, n = i & 63;
        Wop[bfrag_addr(c, n, 8)] = Wo[i];
    }
    if (t < DM) sbo[t] = bo[t];

    int buf = 0;
    for (int tile = blockIdx.x; tile < NROWS / 64; tile += gridDim.x) {
        int nxt = tile + gridDim.x;
        if (nxt < NROWS / 64) {
            const float4* src = (const float4*)(g_attout + (size_t)nxt * 4096) + t;
            #pragma unroll
            for (int u = 0; u < 4; u++)
                cp16(apAddr + (buf ^ 1) * 16384 + u * 4096, src + u * 256);
        }
        CP_COMMIT();
        CP_WAIT1();
        __syncthreads();
        const float* cAp = Apb + buf * 4096;
        size_t row0 = (size_t)tile * 64;

        float acc[2][2][4];
        #pragma unroll
        for (int x = 0; x < 2; x++)
            #pragma unroll
            for (int y = 0; y < 2; y++)
                #pragma unroll
                for (int r = 0; r < 4; r++) acc[x][y][r] = 0.0f;
        #pragma unroll
        for (int ks = 0; ks < 8; ks++) {
            float4 af[2];
            float2 bf[2];
            #pragma unroll
            for (int mt = 0; mt < 2; mt++)
                af[mt] = *(const float4*)&cAp[((wm * 2 + mt) * 8 + ks) * 128 + lane * 4];
            #pragma unroll
            for (int nt = 0; nt < 2; nt++)
                bf[nt] = *(const float2*)&Wop[((wn * 2 + nt) * 8 + ks) * 64 + lane * 2];
            #pragma unroll
            for (int mt = 0; mt < 2; mt++)
                #pragma unroll
                for (int nt = 0; nt < 2; nt++)
                    mma_tf32(acc[mt][nt][0], acc[mt][nt][1], acc[mt][nt][2], acc[mt][nt][3],
                             F2U(af[mt].x), F2U(af[mt].y), F2U(af[mt].z), F2U(af[mt].w),
                             F2U(bf[nt].x), F2U(bf[nt].y));
        }
        #pragma unroll
        for (int mt = 0; mt < 2; mt++) {
            #pragma unroll
            for (int nt = 0; nt < 2; nt++) {
                int rt0 = wm * 32 + mt * 16 + rg;
                int c0 = wn * 16 + nt * 8 + q2;
                float bo0 = sbo[c0], bo1 = sbo[c0 + 1];
                #pragma unroll
                for (int half = 0; half < 2; half++) {
                    size_t r = row0 + rt0 + half * 8;
                    float2 m2 = *(const float2*)&msa[r * DM + c0];
                    *(float2*)&g_msax[r * DM + c0] =
                        make_float2(acc[mt][nt][half * 2]     + bo0 + m2.x,
                                    acc[mt][nt][half * 2 + 1] + bo1 + m2.y);
                }
            }
        }
        __syncthreads();
        buf ^= 1;
    }
}

// =====================================================================
// K6 (mma tf32, 512 threads): fused FF + final LN.
// =====================================================================
struct FFS4 {
    float W1p[DM * FFH];
    float W2p[FFH * DM];
    float b1s[FFH];
    float b2s[DM], g2[DM], bn2[DM], g3[DM], bn3[DM];
    float Xs[64 * DM];
    float Ap[64 * DM];
    float Hp[64 * FFH];
};
extern __shared__ unsigned char ff_raw[];

__global__ void __launch_bounds__(512) ff_mma_kernel(
        const float* __restrict__ n2g, const float* __restrict__ n2b,
        const float* __restrict__ W1, const float* __restrict__ b1,
        const float* __restrict__ W2, const float* __restrict__ b2,
        const float* __restrict__ n3g, const float* __restrict__ n3b,
        float* __restrict__ out) {
    FFS4* s = (FFS4*)ff_raw;
    int t = threadIdx.x, warp = t >> 5, lane = t & 31;
    int rg = lane >> 2, q2 = (lane & 3) * 2;

    for (int i = t; i < DM * FFH; i += 512) {
        int c = i >> 8, n = i & 255;
        s->W1p[bfrag_addr(c, n, 8)] = W1[i];
    }
    for (int i = t; i < FFH * DM; i += 512) {
        int c = i >> 6, n = i & 63;
        s->W2p[bfrag_addr(c, n, 32)] = W2[i];
    }
    if (t < FFH) s->b1s[t] = b1[t];
    if (t < DM) { s->b2s[t] = b2[t]; s->g2[t] = n2g[t]; s->bn2[t] = n2b[t];
                  s->g3[t] = n3g[t]; s->bn3[t] = n3b[t]; }
    __syncthreads();

    const int nTiles = NROWS / 64;
    float4 xr[2];
    if (blockIdx.x < nTiles) {
        const float4* src = (const float4*)&g_msax[(size_t)blockIdx.x * 4096];
        #pragma unroll
        for (int i = 0; i < 2; i++) xr[i] = src[t * 2 + i];
    }

    for (int tile = blockIdx.x; tile < nTiles; tile += gridDim.x) {
        size_t row0 = (size_t)tile * 64;
        #pragma unroll
        for (int i = 0; i < 2; i++)
            *(float4*)&s->Xs[(t * 2 + i) * 4] = xr[i];
        __syncthreads();
        int nxt = tile + gridDim.x;
        if (nxt < nTiles) {
            const float4* src = (const float4*)&g_msax[(size_t)nxt * 4096];
            #pragma unroll
            for (int i = 0; i < 2; i++) xr[i] = src[t * 2 + i];
        }
        #pragma unroll
        for (int rr = 0; rr < 4; rr++) {
            int row = warp * 4 + rr;
            float2 x2 = *(const float2*)&s->Xs[row * DM + 2 * lane];
            float sum = x2.x + x2.y;
            #pragma unroll
            for (int o = 16; o; o >>= 1) sum += __shfl_xor_sync(0xffffffffu, sum, o);
            float m = sum * (1.0f / DM);
            float d0 = x2.x - m, d1 = x2.y - m;
            float vv = d0 * d0 + d1 * d1;
            #pragma unroll
            for (int o = 16; o; o >>= 1) vv += __shfl_xor_sync(0xffffffffu, vv, o);
            float r = rsqrtf(vv * (1.0f / DM) + EPSLN);
            int c0 = 2 * lane;
            s->Ap[afrag_addr(row, c0, 8)]     = d0 * r * s->g2[c0]     + s->bn2[c0];
            s->Ap[afrag_addr(row, c0 + 1, 8)] = d1 * r * s->g2[c0 + 1] + s->bn2[c0 + 1];
        }
        __syncthreads();
        {
            int wm = warp >> 3, wn = warp & 7;
            float acc1[2][4][4];
            #pragma unroll
            for (int x = 0; x < 2; x++)
                #pragma unroll
                for (int y = 0; y < 4; y++)
                    #pragma unroll
                    for (int r = 0; r < 4; r++) acc1[x][y][r] = 0.0f;
            #pragma unroll
            for (int ks = 0; ks < 8; ks++) {
                float4 af0 = *(const float4*)&s->Ap[((wm * 2 + 0) * 8 + ks) * 128 + lane * 4];
                float4 af1 = *(const float4*)&s->Ap[((wm * 2 + 1) * 8 + ks) * 128 + lane * 4];
                #pragma unroll
                for (int nt = 0; nt < 4; nt++) {
                    float2 b2v = *(const float2*)&s->W1p[((wn * 4 + nt) * 8 + ks) * 64 + lane * 2];
                    mma_tf32(acc1[0][nt][0], acc1[0][nt][1], acc1[0][nt][2], acc1[0][nt][3],
                             F2U(af0.x), F2U(af0.y), F2U(af0.z), F2U(af0.w),
                             F2U(b2v.x), F2U(b2v.y));
                    mma_tf32(acc1[1][nt][0], acc1[1][nt][1], acc1[1][nt][2], acc1[1][nt][3],
                             F2U(af1.x), F2U(af1.y), F2U(af1.z), F2U(af1.w),
                             F2U(b2v.x), F2U(b2v.y));
                }
            }
            #pragma unroll
            for (int mt = 0; mt < 2; mt++) {
                int mtg = wm * 2 + mt;
                #pragma unroll
                for (int nt = 0; nt < 4; nt++) {
                    int ks2 = wn * 4 + nt;
                    int c0 = ks2 * 8 + q2;
                    float b1a = s->b1s[c0], b1b = s->b1s[c0 + 1];
                    float v0 = fmaxf(acc1[mt][nt][0] + b1a, 0.f);
                    float v1 = fmaxf(acc1[mt][nt][1] + b1b, 0.f);
                    float v2 = fmaxf(acc1[mt][nt][2] + b1a, 0.f);
                    float v3 = fmaxf(acc1[mt][nt][3] + b1b, 0.f);
                    int fb = (mtg * 32 + ks2) * 128 + rg * 16;
                    int a0 = fb + (q2 & 3) * 4 + ((q2 >> 2) << 1);
                    int kk1 = q2 + 1;
                    int a1 = fb + (kk1 & 3) * 4 + ((kk1 >> 2) << 1);
                    *(float2*)&s->Hp[a0] = make_float2(v0, v2);
                    *(float2*)&s->Hp[a1] = make_float2(v1, v3);
                }
            }
        }
        __syncthreads();
        {
            int kg = warp >> 2;
            int wm2 = (warp >> 1) & 1, wn2 = warp & 1;
            float acc2[2][4][4];
            #pragma unroll
            for (int x = 0; x < 2; x++)
                #pragma unroll
                for (int y = 0; y < 4; y++)
                    #pragma unroll
                    for (int r = 0; r < 4; r++) acc2[x][y][r] = 0.0f;
            #pragma unroll
            for (int ks = 0; ks < 8; ks++) {
                int ksg = kg * 8 + ks;
                float4 af0 = *(const float4*)&s->Hp[((wm2 * 2 + 0) * 32 + ksg) * 128 + lane * 4];
                float4 af1 = *(const float4*)&s->Hp[((wm2 * 2 + 1) * 32 + ksg) * 128 + lane * 4];
                #pragma unroll
                for (int nt = 0; nt < 4; nt++) {
                    float2 b2v = *(const float2*)&s->W2p[((wn2 * 4 + nt) * 32 + ksg) * 64 + lane * 2];
                    mma_tf32(acc2[0][nt][0], acc2[0][nt][1], acc2[0][nt][2], acc2[0][nt][3],
                             F2U(af0.x), F2U(af0.y), F2U(af0.z), F2U(af0.w),
                             F2U(b2v.x), F2U(b2v.y));
                    mma_tf32(acc2[1][nt][0], acc2[1][nt][1], acc2[1][nt][2], acc2[1][nt][3],
                             F2U(af1.x), F2U(af1.y), F2U(af1.z), F2U(af1.w),
                             F2U(b2v.x), F2U(b2v.y));
                }
            }
            __syncthreads();
            float* Ps = s->Ap;
            #pragma unroll
            for (int mt = 0; mt < 2; mt++)
                #pragma unroll
                for (int nt = 0; nt < 4; nt++) {
                    int r0 = wm2 * 32 + mt * 16 + rg;
                    int c0 = wn2 * 32 + nt * 8 + q2;
                    *(float2*)&Ps[kg * 4608 + r0 * 72 + c0] =
                        make_float2(acc2[mt][nt][0], acc2[mt][nt][1]);
                    *(float2*)&Ps[kg * 4608 + (r0 + 8) * 72 + c0] =
                        make_float2(acc2[mt][nt][2], acc2[mt][nt][3]);
                }
        }
        __syncthreads();
        {
            float* Ps = s->Ap;
            #pragma unroll
            for (int rr = 0; rr < 4; rr++) {
                int row = warp * 4 + rr;
                int c0 = 2 * lane;
                float2 x2 = *(const float2*)&s->Xs[row * DM + c0];
                float2 p0 = *(const float2*)&Ps[row * 72 + c0];
                float2 p1 = *(const float2*)&Ps[4608 + row * 72 + c0];
                float2 p2 = *(const float2*)&Ps[9216 + row * 72 + c0];
                float2 p3 = *(const float2*)&Ps[13824 + row * 72 + c0];
                float y0 = x2.x + s->b2s[c0]     + p0.x + p1.x + p2.x + p3.x;
                float y1 = x2.y + s->b2s[c0 + 1] + p0.y + p1.y + p2.y + p3.y;
                float sum = y0 + y1;
                #pragma unroll
                for (int o = 16; o; o >>= 1) sum += __shfl_xor_sync(0xffffffffu, sum, o);
                float m = sum * (1.0f / DM);
                float d0 = y0 - m, d1 = y1 - m;
                float vv = d0 * d0 + d1 * d1;
                #pragma unroll
                for (int o = 16; o; o >>= 1) vv += __shfl_xor_sync(0xffffffffu, vv, o);
                float r = rsqrtf(vv * (1.0f / DM) + EPSLN);
                size_t ob = (row0 + row) * DM;
                out[ob + c0]     = d0 * r * s->g3[c0]     + s->bn3[c0];
                out[ob + c0 + 1] = d1 * r * s->g3[c0 + 1] + s->bn3[c0 + 1];
            }
        }
        __syncthreads();
    }
}

// =====================================================================
extern "C" void kernel_launch(void* const* d_in, const int* in_sizes, int n_in,
                              void* d_out, int out_size) {
    const float* msa   = (const float*)d_in[0];
    const float* Ca    = (const float*)d_in[1];
    const float* state = (const float*)d_in[2];
    const float* ns_g  = (const float*)d_in[3];
    const float* ns_b  = (const float*)d_in[4];
    const float* n1_g  = (const float*)d_in[5];
    const float* n1_b  = (const float*)d_in[6];
    const float* Wq    = (const float*)d_in[7];
    const float* bq    = (const float*)d_in[8];
    const float* Wk    = (const float*)d_in[9];
    const float* bk    = (const float*)d_in[10];
    const float* Wv    = (const float*)d_in[11];
    const float* bv    = (const float*)d_in[12];
    const float* Wo    = (const float*)d_in[13];
    const float* bo    = (const float*)d_in[14];
    const float* n2_g  = (const float*)d_in[15];
    const float* n2_b  = (const float*)d_in[16];
    const float* W1    = (const float*)d_in[17];
    const float* b1    = (const float*)d_in[18];
    const float* W2    = (const float*)d_in[19];
    const float* b2    = (const float*)d_in[20];
    const float* n3_g  = (const float*)d_in[21];
    const float* n3_b  = (const float*)d_in[22];
    float* out = (float*)d_out;

    cudaFuncSetAttribute(ff_mma_kernel, cudaFuncAttributeMaxDynamicSharedMemorySize,
                         (int)sizeof(FFS4));
    cudaFuncSetAttribute(gemm_attn_mma, cudaFuncAttributeMaxDynamicSharedMemorySize,
                         98304);
    cudaFuncSetAttribute(oproj_mma_kernel, cudaFuncAttributeMaxDynamicSharedMemorySize,
                         49152);
    cudaFuncSetAttribute(prep_kernel, cudaFuncAttributeMaxDynamicSharedMemorySize,
                         55296);

    qk_kernel<<<L, 128>>>(state, ns_g, ns_b, Wq, bq, Wk, bk);
    prep_kernel<<<1152, 256, 55296>>>(Ca, msa, n1_g, n1_b, Wv, bv);
    gemm_attn_mma<<<dim3(32, 4, 4), 256, 98304>>>();
    oproj_mma_kernel<<<1024, 256, 49152>>>(msa, Wo, bo);
    ff_mma_kernel<<<148, 512, sizeof(FFS4)>>>(n2_g, n2_b, W1, b1, W2, b2, n3_g, n3_b, out);
}